// round 2
// baseline (speedup 1.0000x reference)
#include <cuda_runtime.h>
#include <math.h>
#include <stdint.h>

#define ND   64
#define ED   32
#define HID  256
#define MSGD 128
#define MAX_EDGES 800000
#define MAX_NODES 50000

#define BM    64
#define HPAD  260     // 256 padded: stride%32==4 -> conflict-free
#define EPAD  36      // 32 padded
#define APAD  68      // 64 padded
#define XPAD  132     // 128 padded
#define PROJW 512     // [Ps(256) | Pr(256)] per node

// ---- scratch (device globals; no runtime allocation allowed) ----
__device__ int   g_count;
__device__ int   g_active[MAX_EDGES];
__device__ int   g_crecv[MAX_EDGES];
__device__ float g_msg[(size_t)MAX_EDGES * MSGD];
__device__ float g_logits[MAX_EDGES];
__device__ float g_e[MAX_EDGES];
__device__ float g_segmax[MAX_NODES];
__device__ float g_denom[MAX_NODES];
__device__ float g_aggr[(size_t)MAX_NODES * MSGD];
__device__ float g_proj[(size_t)MAX_NODES * PROJW];

// ---------------- init ----------------
__global__ void init_kernel(int n_agents) {
    int i = blockIdx.x * blockDim.x + threadIdx.x;
    int total = n_agents * MSGD;
    if (i < total) g_aggr[i] = 0.f;
    if (i < n_agents) { g_segmax[i] = -INFINITY; g_denom[i] = 0.f; }
    if (i == 0) g_count = 0;
}

// ---------------- compact: keep only edges whose receiver is an agent --------
__global__ void compact_kernel(const int* __restrict__ recv, int n_edges, int n_agents) {
    int i = blockIdx.x * blockDim.x + threadIdx.x;
    if (i >= n_edges) return;
    int r = recv[i];
    if (r < n_agents) {
        int p = atomicAdd(&g_count, 1);
        g_active[p] = i;
        g_crecv[p]  = r;
    }
}

// ---------------- node projections: P = node_feats @ [W1_s | W1_r] ----------
// grid = (ceil(n/64), 2); by=0 -> W1 rows 0..63 -> cols [0,256)
//                         by=1 -> W1 rows 64..127 -> cols [256,512)
__global__ __launch_bounds__(256, 2) void node_proj_kernel(
    const float* __restrict__ node_feats, const float* __restrict__ W1, int n_nodes)
{
    __shared__ float s_a[BM][APAD];
    const int r0 = blockIdx.x * BM;
    const int by = blockIdx.y;
    const int tid = threadIdx.x;

    for (int idx = tid; idx < BM * 16; idx += 256) {
        int m = idx >> 4, p = idx & 15;
        int row = r0 + m;
        float4 v = make_float4(0.f, 0.f, 0.f, 0.f);
        if (row < n_nodes) v = ((const float4*)(node_feats + (size_t)row * ND))[p];
        *(float4*)&s_a[m][p * 4] = v;
    }
    __syncthreads();

    const int tx = tid & 15, ty = tid >> 4;
    const int n0 = tx * 16, m0 = ty * 4;
    const float* Wblk = W1 + (size_t)(by * 64) * HID;

    float acc[4][16];
    #pragma unroll
    for (int i = 0; i < 4; i++)
        #pragma unroll
        for (int j = 0; j < 16; j++) acc[i][j] = 0.f;

    #pragma unroll 2
    for (int k = 0; k < 64; k++) {
        float a0 = s_a[m0 + 0][k], a1 = s_a[m0 + 1][k];
        float a2 = s_a[m0 + 2][k], a3 = s_a[m0 + 3][k];
        const float* wr = Wblk + k * HID + n0;
        float4 w0 = *(const float4*)(wr);
        float4 w1 = *(const float4*)(wr + 4);
        float4 w2 = *(const float4*)(wr + 8);
        float4 w3 = *(const float4*)(wr + 12);
        float w[16] = {w0.x,w0.y,w0.z,w0.w, w1.x,w1.y,w1.z,w1.w,
                       w2.x,w2.y,w2.z,w2.w, w3.x,w3.y,w3.z,w3.w};
        #pragma unroll
        for (int j = 0; j < 16; j++) {
            acc[0][j] = fmaf(a0, w[j], acc[0][j]);
            acc[1][j] = fmaf(a1, w[j], acc[1][j]);
            acc[2][j] = fmaf(a2, w[j], acc[2][j]);
            acc[3][j] = fmaf(a3, w[j], acc[3][j]);
        }
    }
    #pragma unroll
    for (int i = 0; i < 4; i++) {
        int row = r0 + m0 + i;
        if (row < n_nodes) {
            float* dst = g_proj + (size_t)row * PROJW + by * 256 + n0;
            #pragma unroll
            for (int g = 0; g < 4; g++)
                *(float4*)(dst + g * 4) = make_float4(acc[i][g*4+0], acc[i][g*4+1],
                                                      acc[i][g*4+2], acc[i][g*4+3]);
        }
    }
}

// ---------------- fused edge MLP: h = relu(Ps+Pr+E@W1e+b1); msg; logits -----
__global__ __launch_bounds__(256, 2) void edge_mlp_kernel(
    const float* __restrict__ edge_feats,
    const float* __restrict__ W1, const float* __restrict__ b1,
    const float* __restrict__ W2, const float* __restrict__ b2,
    const float* __restrict__ w_gate, const float* __restrict__ b_gate,
    const int* __restrict__ senders)
{
    extern __shared__ float smem[];
    float (*s_e)[EPAD] = (float (*)[EPAD])smem;                  // 64 x 36
    float (*s_h)[HPAD] = (float (*)[HPAD])(smem + BM * EPAD);    // 64 x 260
    int* s_is   = (int*)(smem + BM * EPAD + BM * HPAD);          // sender idx
    int* s_ir   = s_is + BM;                                     // receiver idx
    int* s_eidx = s_ir + BM;                                     // raw edge idx

    const int cnt = g_count;
    const int e0  = blockIdx.x * BM;
    if (e0 >= cnt) return;
    const int tid = threadIdx.x;

    if (tid < BM) {
        int ci = e0 + tid;
        int e = 0, s = 0, r = 0;
        if (ci < cnt) { e = g_active[ci]; s = senders[e]; r = g_crecv[ci]; }
        s_eidx[tid] = e; s_is[tid] = s; s_ir[tid] = r;
    }
    __syncthreads();

    // edge feats: 64 edges x 8 float4
    for (int idx = tid; idx < BM * 8; idx += 256) {
        int m = idx >> 3, p = idx & 7;
        float4 v = make_float4(0.f, 0.f, 0.f, 0.f);
        if (e0 + m < cnt) v = ((const float4*)(edge_feats + (size_t)s_eidx[m] * ED))[p];
        *(float4*)&s_e[m][p * 4] = v;
    }
    __syncthreads();

    const int tx = tid & 15, ty = tid >> 4;
    const int n0 = tx * 16, m0 = ty * 4;

    // ---- edge-proj GEMM (K=32) + bias ----
    float acc[4][16];
    {
        float bv[16];
        *(float4*)&bv[0]  = *(const float4*)(b1 + n0);
        *(float4*)&bv[4]  = *(const float4*)(b1 + n0 + 4);
        *(float4*)&bv[8]  = *(const float4*)(b1 + n0 + 8);
        *(float4*)&bv[12] = *(const float4*)(b1 + n0 + 12);
        #pragma unroll
        for (int i = 0; i < 4; i++)
            #pragma unroll
            for (int j = 0; j < 16; j++) acc[i][j] = bv[j];
    }
    const float* W1e = W1 + (size_t)(2 * ND) * HID;   // rows 128..159
    #pragma unroll 2
    for (int k = 0; k < ED; k++) {
        float a0 = s_e[m0 + 0][k], a1 = s_e[m0 + 1][k];
        float a2 = s_e[m0 + 2][k], a3 = s_e[m0 + 3][k];
        const float* wr = W1e + k * HID + n0;
        float4 w0 = *(const float4*)(wr);
        float4 w1 = *(const float4*)(wr + 4);
        float4 w2 = *(const float4*)(wr + 8);
        float4 w3 = *(const float4*)(wr + 12);
        float w[16] = {w0.x,w0.y,w0.z,w0.w, w1.x,w1.y,w1.z,w1.w,
                       w2.x,w2.y,w2.z,w2.w, w3.x,w3.y,w3.z,w3.w};
        #pragma unroll
        for (int j = 0; j < 16; j++) {
            acc[0][j] = fmaf(a0, w[j], acc[0][j]);
            acc[1][j] = fmaf(a1, w[j], acc[1][j]);
            acc[2][j] = fmaf(a2, w[j], acc[2][j]);
            acc[3][j] = fmaf(a3, w[j], acc[3][j]);
        }
    }

    // ---- add gathered node projections, relu, write h tile ----
    #pragma unroll
    for (int i = 0; i < 4; i++) {
        int m = m0 + i;
        const float* ps = g_proj + (size_t)s_is[m] * PROJW + n0;         // sender block
        const float* pr = g_proj + (size_t)s_ir[m] * PROJW + 256 + n0;   // receiver block
        #pragma unroll
        for (int g = 0; g < 4; g++) {
            float4 a = *(const float4*)(ps + g * 4);
            float4 b = *(const float4*)(pr + g * 4);
            float4 r;
            r.x = fmaxf(acc[i][g*4+0] + a.x + b.x, 0.f);
            r.y = fmaxf(acc[i][g*4+1] + a.y + b.y, 0.f);
            r.z = fmaxf(acc[i][g*4+2] + a.z + b.z, 0.f);
            r.w = fmaxf(acc[i][g*4+3] + a.w + b.w, 0.f);
            *(float4*)&s_h[m][n0 + g * 4] = r;
        }
    }
    __syncthreads();

    // ---- GEMM2: [64x256] @ [256x128], per-thread 4x8 ----
    const int c0 = tx * 8;
    float acc2[4][8];
    {
        float bv[8];
        *(float4*)&bv[0] = *(const float4*)(b2 + c0);
        *(float4*)&bv[4] = *(const float4*)(b2 + c0 + 4);
        #pragma unroll
        for (int i = 0; i < 4; i++)
            #pragma unroll
            for (int j = 0; j < 8; j++) acc2[i][j] = bv[j];
    }
    #pragma unroll 2
    for (int k = 0; k < HID; k++) {
        float a0 = s_h[m0 + 0][k], a1 = s_h[m0 + 1][k];
        float a2 = s_h[m0 + 2][k], a3 = s_h[m0 + 3][k];
        const float* wr = W2 + k * MSGD + c0;
        float4 w0 = *(const float4*)(wr);
        float4 w1 = *(const float4*)(wr + 4);
        float w[8] = {w0.x,w0.y,w0.z,w0.w, w1.x,w1.y,w1.z,w1.w};
        #pragma unroll
        for (int j = 0; j < 8; j++) {
            acc2[0][j] = fmaf(a0, w[j], acc2[0][j]);
            acc2[1][j] = fmaf(a1, w[j], acc2[1][j]);
            acc2[2][j] = fmaf(a2, w[j], acc2[2][j]);
            acc2[3][j] = fmaf(a3, w[j], acc2[3][j]);
        }
    }

    // relu + gate partials + store msg
    float wg[8];
    *(float4*)&wg[0] = *(const float4*)(w_gate + c0);
    *(float4*)&wg[4] = *(const float4*)(w_gate + c0 + 4);
    float partial[4];
    #pragma unroll
    for (int i = 0; i < 4; i++) {
        float p = 0.f;
        #pragma unroll
        for (int j = 0; j < 8; j++) {
            float v = fmaxf(acc2[i][j], 0.f);
            acc2[i][j] = v;
            p = fmaf(v, wg[j], p);
        }
        partial[i] = p;
        int ci = e0 + m0 + i;
        if (ci < cnt) {
            float* dst = g_msg + (size_t)ci * MSGD + c0;
            *(float4*)(dst)     = make_float4(acc2[i][0], acc2[i][1], acc2[i][2], acc2[i][3]);
            *(float4*)(dst + 4) = make_float4(acc2[i][4], acc2[i][5], acc2[i][6], acc2[i][7]);
        }
    }
    #pragma unroll
    for (int o = 8; o >= 1; o >>= 1) {
        #pragma unroll
        for (int i = 0; i < 4; i++)
            partial[i] += __shfl_xor_sync(0xffffffffu, partial[i], o);
    }
    if (tx == 0) {
        float bg = b_gate[0];
        #pragma unroll
        for (int i = 0; i < 4; i++) {
            int ci = e0 + m0 + i;
            if (ci < cnt) g_logits[ci] = partial[i] + bg;
        }
    }
}

// ---------------- segment max (exact, sign-split int atomics) ----------------
__global__ void seg_max_kernel() {
    int i = blockIdx.x * blockDim.x + threadIdx.x;
    if (i >= g_count) return;
    float v = g_logits[i];
    int r = g_crecv[i];
    if (v >= 0.f) atomicMax((int*)(g_segmax + r), __float_as_int(v));
    else          atomicMin((unsigned int*)(g_segmax + r), (unsigned int)__float_as_int(v));
}

// ---------------- exp + segment denom ----------------------------------------
__global__ void exp_denom_kernel() {
    int i = blockIdx.x * blockDim.x + threadIdx.x;
    if (i >= g_count) return;
    int r = g_crecv[i];
    float ev = expf(g_logits[i] - g_segmax[r]);
    g_e[i] = ev;
    atomicAdd(g_denom + r, ev);
}

// ---------------- weighted scatter-add: one warp per edge --------------------
__global__ void aggr_kernel() {
    int w = (blockIdx.x * blockDim.x + threadIdx.x) >> 5;
    if (w >= g_count) return;
    int lane = threadIdx.x & 31;
    int r = g_crecv[w];
    float coef = g_e[w] / (g_denom[r] + 1e-9f);
    float4 mv = *(const float4*)(g_msg + (size_t)w * MSGD + lane * 4);
    float* dst = g_aggr + (size_t)r * MSGD + lane * 4;
    atomicAdd(dst + 0, coef * mv.x);
    atomicAdd(dst + 1, coef * mv.y);
    atomicAdd(dst + 2, coef * mv.z);
    atomicAdd(dst + 3, coef * mv.w);
}

// ---------------- agent MLP ---------------------------------------------------
__global__ __launch_bounds__(256, 2) void agent_mlp_kernel(
    const float* __restrict__ W_h1, const float* __restrict__ b_h1,
    const float* __restrict__ W_h2, const float* __restrict__ b_h2,
    const float* __restrict__ W_out, const float* __restrict__ b_out,
    float* __restrict__ out, int n_agents)
{
    extern __shared__ float smem[];
    float (*s_x)[XPAD] = (float (*)[XPAD])smem;
    float (*s_h)[HPAD] = (float (*)[HPAD])(smem + BM * XPAD);

    const int r0 = blockIdx.x * BM;
    const int tid = threadIdx.x;

    for (int idx = tid; idx < BM * 32; idx += 256) {
        int m = idx >> 5, p = idx & 31;
        int r = r0 + m;
        float4 v = make_float4(0.f, 0.f, 0.f, 0.f);
        if (r < n_agents) v = *(const float4*)(g_aggr + (size_t)r * MSGD + p * 4);
        *(float4*)&s_x[m][p * 4] = v;
    }
    __syncthreads();

    const int tx = tid & 15, ty = tid >> 4;
    const int n0 = tx * 16, m0 = ty * 4;

    float acc[4][16];
    {
        float bv[16];
        *(float4*)&bv[0]  = *(const float4*)(b_h1 + n0);
        *(float4*)&bv[4]  = *(const float4*)(b_h1 + n0 + 4);
        *(float4*)&bv[8]  = *(const float4*)(b_h1 + n0 + 8);
        *(float4*)&bv[12] = *(const float4*)(b_h1 + n0 + 12);
        #pragma unroll
        for (int i = 0; i < 4; i++)
            #pragma unroll
            for (int j = 0; j < 16; j++) acc[i][j] = bv[j];
    }
    #pragma unroll 2
    for (int k = 0; k < MSGD; k++) {
        float a0 = s_x[m0 + 0][k], a1 = s_x[m0 + 1][k];
        float a2 = s_x[m0 + 2][k], a3 = s_x[m0 + 3][k];
        const float* wr = W_h1 + k * HID + n0;
        float4 w0 = *(const float4*)(wr);
        float4 w1 = *(const float4*)(wr + 4);
        float4 w2 = *(const float4*)(wr + 8);
        float4 w3 = *(const float4*)(wr + 12);
        float w[16] = {w0.x,w0.y,w0.z,w0.w, w1.x,w1.y,w1.z,w1.w,
                       w2.x,w2.y,w2.z,w2.w, w3.x,w3.y,w3.z,w3.w};
        #pragma unroll
        for (int j = 0; j < 16; j++) {
            acc[0][j] = fmaf(a0, w[j], acc[0][j]);
            acc[1][j] = fmaf(a1, w[j], acc[1][j]);
            acc[2][j] = fmaf(a2, w[j], acc[2][j]);
            acc[3][j] = fmaf(a3, w[j], acc[3][j]);
        }
    }
    #pragma unroll
    for (int i = 0; i < 4; i++) {
        #pragma unroll
        for (int g = 0; g < 4; g++) {
            float4 r;
            r.x = fmaxf(acc[i][g*4+0], 0.f); r.y = fmaxf(acc[i][g*4+1], 0.f);
            r.z = fmaxf(acc[i][g*4+2], 0.f); r.w = fmaxf(acc[i][g*4+3], 0.f);
            *(float4*)&s_h[m0 + i][n0 + g * 4] = r;
        }
    }
    __syncthreads();

    {
        float bv[16];
        *(float4*)&bv[0]  = *(const float4*)(b_h2 + n0);
        *(float4*)&bv[4]  = *(const float4*)(b_h2 + n0 + 4);
        *(float4*)&bv[8]  = *(const float4*)(b_h2 + n0 + 8);
        *(float4*)&bv[12] = *(const float4*)(b_h2 + n0 + 12);
        #pragma unroll
        for (int i = 0; i < 4; i++)
            #pragma unroll
            for (int j = 0; j < 16; j++) acc[i][j] = bv[j];
    }
    #pragma unroll 2
    for (int k = 0; k < HID; k++) {
        float a0 = s_h[m0 + 0][k], a1 = s_h[m0 + 1][k];
        float a2 = s_h[m0 + 2][k], a3 = s_h[m0 + 3][k];
        const float* wr = W_h2 + k * HID + n0;
        float4 w0 = *(const float4*)(wr);
        float4 w1 = *(const float4*)(wr + 4);
        float4 w2 = *(const float4*)(wr + 8);
        float4 w3 = *(const float4*)(wr + 12);
        float w[16] = {w0.x,w0.y,w0.z,w0.w, w1.x,w1.y,w1.z,w1.w,
                       w2.x,w2.y,w2.z,w2.w, w3.x,w3.y,w3.z,w3.w};
        #pragma unroll
        for (int j = 0; j < 16; j++) {
            acc[0][j] = fmaf(a0, w[j], acc[0][j]);
            acc[1][j] = fmaf(a1, w[j], acc[1][j]);
            acc[2][j] = fmaf(a2, w[j], acc[2][j]);
            acc[3][j] = fmaf(a3, w[j], acc[3][j]);
        }
    }

    float wo[16];
    *(float4*)&wo[0]  = *(const float4*)(W_out + n0);
    *(float4*)&wo[4]  = *(const float4*)(W_out + n0 + 4);
    *(float4*)&wo[8]  = *(const float4*)(W_out + n0 + 8);
    *(float4*)&wo[12] = *(const float4*)(W_out + n0 + 12);
    float partial[4];
    #pragma unroll
    for (int i = 0; i < 4; i++) {
        float p = 0.f;
        #pragma unroll
        for (int j = 0; j < 16; j++)
            p = fmaf(fmaxf(acc[i][j], 0.f), wo[j], p);
        partial[i] = p;
    }
    #pragma unroll
    for (int o = 8; o >= 1; o >>= 1) {
        #pragma unroll
        for (int i = 0; i < 4; i++)
            partial[i] += __shfl_xor_sync(0xffffffffu, partial[i], o);
    }
    if (tx == 0) {
        float bo = b_out[0];
        #pragma unroll
        for (int i = 0; i < 4; i++) {
            int r = r0 + m0 + i;
            if (r < n_agents) out[r] = tanhf(partial[i] + bo);
        }
    }
}

// ---------------------------------------------------------------------------
extern "C" void kernel_launch(void* const* d_in, const int* in_sizes, int n_in,
                              void* d_out, int out_size) {
    const float* node_feats = (const float*)d_in[0];
    const float* edge_feats = (const float*)d_in[1];
    const float* W_msg1 = (const float*)d_in[2];
    const float* b_msg1 = (const float*)d_in[3];
    const float* W_msg2 = (const float*)d_in[4];
    const float* b_msg2 = (const float*)d_in[5];
    const float* w_gate = (const float*)d_in[6];
    const float* b_gate = (const float*)d_in[7];
    const float* W_h1   = (const float*)d_in[8];
    const float* b_h1   = (const float*)d_in[9];
    const float* W_h2   = (const float*)d_in[10];
    const float* b_h2   = (const float*)d_in[11];
    const float* W_out  = (const float*)d_in[12];
    const float* b_out  = (const float*)d_in[13];
    const int* senders   = (const int*)d_in[14];
    const int* receivers = (const int*)d_in[15];
    float* out = (float*)d_out;

    const int n_edges  = in_sizes[14];
    const int n_nodes  = in_sizes[0] / ND;
    const int n_agents = out_size;

    const int SMEM_EDGE  = (BM * EPAD + BM * HPAD) * (int)sizeof(float) + 3 * BM * (int)sizeof(int);
    const int SMEM_AGENT = (BM * XPAD + BM * HPAD) * (int)sizeof(float);
    cudaFuncSetAttribute(edge_mlp_kernel, cudaFuncAttributeMaxDynamicSharedMemorySize, SMEM_EDGE);
    cudaFuncSetAttribute(agent_mlp_kernel, cudaFuncAttributeMaxDynamicSharedMemorySize, SMEM_AGENT);

    // 1. init scratch
    {
        int total = n_agents * MSGD;
        init_kernel<<<(total + 255) / 256, 256>>>(n_agents);
    }
    // 2. compact edges with receiver < n_agents
    compact_kernel<<<(n_edges + 255) / 256, 256>>>(receivers, n_edges, n_agents);
    // 3. per-node projections (independent of compaction)
    {
        dim3 grid((n_nodes + BM - 1) / BM, 2);
        node_proj_kernel<<<grid, 256>>>(node_feats, W_msg1, n_nodes);
    }
    // 4. fused edge MLP over compacted edges
    {
        int grid = (n_edges + BM - 1) / BM;
        edge_mlp_kernel<<<grid, 256, SMEM_EDGE>>>(
            edge_feats, W_msg1, b_msg1, W_msg2, b_msg2, w_gate, b_gate, senders);
    }
    // 5-6. segment softmax
    seg_max_kernel<<<(n_edges + 255) / 256, 256>>>();
    exp_denom_kernel<<<(n_edges + 255) / 256, 256>>>();
    // 7. weighted scatter-add (one warp per edge)
    {
        long long warps = n_edges;
        int grid = (int)((warps * 32 + 255) / 256);
        aggr_kernel<<<grid, 256>>>();
    }
    // 8. agent MLP
    agent_mlp_kernel<<<(n_agents + BM - 1) / BM, 256, SMEM_AGENT>>>(
        W_h1, b_h1, W_h2, b_h2, W_out, b_out, out, n_agents);
}

// round 3
// speedup vs baseline: 1.5819x; 1.5819x over previous
#include <cuda_runtime.h>
#include <math.h>
#include <stdint.h>

#define ND   64
#define ED   32
#define HID  256
#define MSGD 128
#define MAX_EDGES 800000
#define MAX_NODES 50000

#define BM    64
#define HPAD  260     // 256 padded: stride%32==4 -> conflict-free
#define EPAD  36
#define APAD  68
#define XPAD  132
#define PROJW 512     // [Ps(256) | Pr(256)] per node

typedef unsigned long long u64;

// ---- packed f32x2 helpers (sm_103a FFMA2 path) ----
__device__ __forceinline__ u64 ffma2(u64 a, u64 b, u64 c) {
    u64 d;
    asm("fma.rn.f32x2 %0, %1, %2, %3;" : "=l"(d) : "l"(a), "l"(b), "l"(c));
    return d;
}
__device__ __forceinline__ u64 pack2(float x) {
    u64 r;
    asm("mov.b64 %0, {%1, %1};" : "=l"(r) : "f"(x));
    return r;
}
__device__ __forceinline__ float2 unpack2(u64 v) {
    float2 f;
    asm("mov.b64 {%0, %1}, %2;" : "=f"(f.x), "=f"(f.y) : "l"(v));
    return f;
}

// ---- scratch ----
__device__ int   g_count;
__device__ int   g_active[MAX_EDGES];
__device__ int   g_crecv[MAX_EDGES];
__device__ float g_msg[(size_t)MAX_EDGES * MSGD];
__device__ float g_logits[MAX_EDGES];
__device__ float g_e[MAX_EDGES];
__device__ float g_segmax[MAX_NODES];
__device__ float g_denom[MAX_NODES];
__device__ float g_aggr[(size_t)MAX_NODES * MSGD];
__device__ float g_proj[(size_t)MAX_NODES * PROJW];

// ---------------- init ----------------
__global__ void init_kernel(int n_agents) {
    int i = blockIdx.x * blockDim.x + threadIdx.x;
    int total = n_agents * MSGD;
    if (i < total) g_aggr[i] = 0.f;
    if (i < n_agents) { g_segmax[i] = -INFINITY; g_denom[i] = 0.f; }
    if (i == 0) g_count = 0;
}

// ---------------- compact ----------------
__global__ void compact_kernel(const int* __restrict__ recv, int n_edges, int n_agents) {
    int i = blockIdx.x * blockDim.x + threadIdx.x;
    if (i >= n_edges) return;
    int r = recv[i];
    if (r < n_agents) {
        int p = atomicAdd(&g_count, 1);
        g_active[p] = i;
        g_crecv[p]  = r;
    }
}

// ---------------- node projections: P = node_feats @ [W1_s | W1_r] ----------
__global__ __launch_bounds__(256, 2) void node_proj_kernel(
    const float* __restrict__ node_feats, const float* __restrict__ W1, int n_nodes)
{
    __shared__ float s_a[BM][APAD];
    const int r0 = blockIdx.x * BM;
    const int by = blockIdx.y;
    const int tid = threadIdx.x;

    for (int idx = tid; idx < BM * 16; idx += 256) {
        int m = idx >> 4, p = idx & 15;
        int row = r0 + m;
        float4 v = make_float4(0.f, 0.f, 0.f, 0.f);
        if (row < n_nodes) v = ((const float4*)(node_feats + (size_t)row * ND))[p];
        *(float4*)&s_a[m][p * 4] = v;
    }
    __syncthreads();

    const int tx = tid & 15, ty = tid >> 4;
    const int n0 = tx * 16, m0 = ty * 4;
    const float* Wblk = W1 + (size_t)(by * 64) * HID;

    u64 acc[4][8];
    #pragma unroll
    for (int i = 0; i < 4; i++)
        #pragma unroll
        for (int p = 0; p < 8; p++) acc[i][p] = 0ull;

    #pragma unroll 2
    for (int k = 0; k < 64; k++) {
        u64 a0 = pack2(s_a[m0 + 0][k]), a1 = pack2(s_a[m0 + 1][k]);
        u64 a2 = pack2(s_a[m0 + 2][k]), a3 = pack2(s_a[m0 + 3][k]);
        const ulonglong2* wp = (const ulonglong2*)(Wblk + k * HID + n0);
        ulonglong2 w0 = wp[0], w1 = wp[1], w2 = wp[2], w3 = wp[3];
        u64 w[8] = {w0.x, w0.y, w1.x, w1.y, w2.x, w2.y, w3.x, w3.y};
        #pragma unroll
        for (int p = 0; p < 8; p++) {
            acc[0][p] = ffma2(a0, w[p], acc[0][p]);
            acc[1][p] = ffma2(a1, w[p], acc[1][p]);
            acc[2][p] = ffma2(a2, w[p], acc[2][p]);
            acc[3][p] = ffma2(a3, w[p], acc[3][p]);
        }
    }
    #pragma unroll
    for (int i = 0; i < 4; i++) {
        int row = r0 + m0 + i;
        if (row < n_nodes) {
            float* dst = g_proj + (size_t)row * PROJW + by * 256 + n0;
            #pragma unroll
            for (int g = 0; g < 4; g++) {
                float2 u0 = unpack2(acc[i][2 * g]);
                float2 u1 = unpack2(acc[i][2 * g + 1]);
                *(float4*)(dst + g * 4) = make_float4(u0.x, u0.y, u1.x, u1.y);
            }
        }
    }
}

// ---------------- fused edge MLP ---------------------------------------------
__global__ __launch_bounds__(256, 2) void edge_mlp_kernel(
    const float* __restrict__ edge_feats,
    const float* __restrict__ W1, const float* __restrict__ b1,
    const float* __restrict__ W2, const float* __restrict__ b2,
    const float* __restrict__ w_gate, const float* __restrict__ b_gate,
    const int* __restrict__ senders)
{
    extern __shared__ float smem[];
    float (*s_e)[EPAD] = (float (*)[EPAD])smem;                  // 64 x 36
    float (*s_h)[HPAD] = (float (*)[HPAD])(smem + BM * EPAD);    // 64 x 260
    int* s_is   = (int*)(smem + BM * EPAD + BM * HPAD);
    int* s_ir   = s_is + BM;
    int* s_eidx = s_ir + BM;

    const int cnt = g_count;
    const int e0  = blockIdx.x * BM;
    if (e0 >= cnt) return;
    const int tid = threadIdx.x;

    if (tid < BM) {
        int ci = e0 + tid;
        int e = 0, s = 0, r = 0;
        if (ci < cnt) { e = g_active[ci]; s = senders[e]; r = g_crecv[ci]; }
        s_eidx[tid] = e; s_is[tid] = s; s_ir[tid] = r;
    }
    __syncthreads();

    // pre-sum Ps + Pr into s_h (coalesced, deep load pipeline) + edge feats
    for (int idx = tid; idx < BM * 64; idx += 256) {
        int m = idx >> 6, p = idx & 63;
        const float4 a = *(const float4*)(g_proj + (size_t)s_is[m] * PROJW + p * 4);
        const float4 b = *(const float4*)(g_proj + (size_t)s_ir[m] * PROJW + 256 + p * 4);
        *(float4*)&s_h[m][p * 4] = make_float4(a.x + b.x, a.y + b.y, a.z + b.z, a.w + b.w);
    }
    for (int idx = tid; idx < BM * 8; idx += 256) {
        int m = idx >> 3, p = idx & 7;
        float4 v = make_float4(0.f, 0.f, 0.f, 0.f);
        if (e0 + m < cnt) v = ((const float4*)(edge_feats + (size_t)s_eidx[m] * ED))[p];
        *(float4*)&s_e[m][p * 4] = v;
    }
    __syncthreads();

    const int tx = tid & 15, ty = tid >> 4;
    const int n0 = tx * 16, m0 = ty * 4;

    // ---- edge-proj GEMM (K=32) + bias, packed ----
    u64 acc[4][8];
    {
        const u64* bp = (const u64*)(b1 + n0);
        u64 bv[8];
        #pragma unroll
        for (int p = 0; p < 8; p++) bv[p] = bp[p];
        #pragma unroll
        for (int i = 0; i < 4; i++)
            #pragma unroll
            for (int p = 0; p < 8; p++) acc[i][p] = bv[p];
    }
    const float* W1e = W1 + (size_t)(2 * ND) * HID;
    #pragma unroll 2
    for (int k = 0; k < ED; k++) {
        u64 a0 = pack2(s_e[m0 + 0][k]), a1 = pack2(s_e[m0 + 1][k]);
        u64 a2 = pack2(s_e[m0 + 2][k]), a3 = pack2(s_e[m0 + 3][k]);
        const ulonglong2* wp = (const ulonglong2*)(W1e + k * HID + n0);
        ulonglong2 w0 = wp[0], w1 = wp[1], w2 = wp[2], w3 = wp[3];
        u64 w[8] = {w0.x, w0.y, w1.x, w1.y, w2.x, w2.y, w3.x, w3.y};
        #pragma unroll
        for (int p = 0; p < 8; p++) {
            acc[0][p] = ffma2(a0, w[p], acc[0][p]);
            acc[1][p] = ffma2(a1, w[p], acc[1][p]);
            acc[2][p] = ffma2(a2, w[p], acc[2][p]);
            acc[3][p] = ffma2(a3, w[p], acc[3][p]);
        }
    }

    // h = relu(acc + presummed projections), write back to s_h
    #pragma unroll
    for (int i = 0; i < 4; i++) {
        int m = m0 + i;
        #pragma unroll
        for (int g = 0; g < 4; g++) {
            float4 hv = *(float4*)&s_h[m][n0 + g * 4];
            float2 u0 = unpack2(acc[i][2 * g]);
            float2 u1 = unpack2(acc[i][2 * g + 1]);
            float4 r;
            r.x = fmaxf(u0.x + hv.x, 0.f);
            r.y = fmaxf(u0.y + hv.y, 0.f);
            r.z = fmaxf(u1.x + hv.z, 0.f);
            r.w = fmaxf(u1.y + hv.w, 0.f);
            *(float4*)&s_h[m][n0 + g * 4] = r;
        }
    }
    __syncthreads();

    // ---- GEMM2: [64x256] @ [256x128], packed, per-thread 4x8 ----
    const int c0 = tx * 8;
    u64 acc2[4][4];
    {
        const u64* bp = (const u64*)(b2 + c0);
        u64 bv[4] = {bp[0], bp[1], bp[2], bp[3]};
        #pragma unroll
        for (int i = 0; i < 4; i++)
            #pragma unroll
            for (int p = 0; p < 4; p++) acc2[i][p] = bv[p];
    }
    #pragma unroll 4
    for (int k = 0; k < HID; k++) {
        u64 a0 = pack2(s_h[m0 + 0][k]), a1 = pack2(s_h[m0 + 1][k]);
        u64 a2 = pack2(s_h[m0 + 2][k]), a3 = pack2(s_h[m0 + 3][k]);
        const ulonglong2* wp = (const ulonglong2*)(W2 + k * MSGD + c0);
        ulonglong2 w0 = wp[0], w1 = wp[1];
        u64 w[4] = {w0.x, w0.y, w1.x, w1.y};
        #pragma unroll
        for (int p = 0; p < 4; p++) {
            acc2[0][p] = ffma2(a0, w[p], acc2[0][p]);
            acc2[1][p] = ffma2(a1, w[p], acc2[1][p]);
            acc2[2][p] = ffma2(a2, w[p], acc2[2][p]);
            acc2[3][p] = ffma2(a3, w[p], acc2[3][p]);
        }
    }

    // relu + gate partials + store msg
    float wg[8];
    *(float4*)&wg[0] = *(const float4*)(w_gate + c0);
    *(float4*)&wg[4] = *(const float4*)(w_gate + c0 + 4);
    float partial[4];
    #pragma unroll
    for (int i = 0; i < 4; i++) {
        float v[8];
        #pragma unroll
        for (int p = 0; p < 4; p++) {
            float2 u = unpack2(acc2[i][p]);
            v[2 * p]     = fmaxf(u.x, 0.f);
            v[2 * p + 1] = fmaxf(u.y, 0.f);
        }
        float s = 0.f;
        #pragma unroll
        for (int j = 0; j < 8; j++) s = fmaf(v[j], wg[j], s);
        partial[i] = s;
        int ci = e0 + m0 + i;
        if (ci < cnt) {
            float* dst = g_msg + (size_t)ci * MSGD + c0;
            *(float4*)(dst)     = make_float4(v[0], v[1], v[2], v[3]);
            *(float4*)(dst + 4) = make_float4(v[4], v[5], v[6], v[7]);
        }
    }
    #pragma unroll
    for (int o = 8; o >= 1; o >>= 1) {
        #pragma unroll
        for (int i = 0; i < 4; i++)
            partial[i] += __shfl_xor_sync(0xffffffffu, partial[i], o);
    }
    if (tx == 0) {
        float bg = b_gate[0];
        #pragma unroll
        for (int i = 0; i < 4; i++) {
            int ci = e0 + m0 + i;
            if (ci < cnt) g_logits[ci] = partial[i] + bg;
        }
    }
}

// ---------------- segment max ----------------
__global__ void seg_max_kernel() {
    int i = blockIdx.x * blockDim.x + threadIdx.x;
    if (i >= g_count) return;
    float v = g_logits[i];
    int r = g_crecv[i];
    if (v >= 0.f) atomicMax((int*)(g_segmax + r), __float_as_int(v));
    else          atomicMin((unsigned int*)(g_segmax + r), (unsigned int)__float_as_int(v));
}

// ---------------- exp + denom ----------------
__global__ void exp_denom_kernel() {
    int i = blockIdx.x * blockDim.x + threadIdx.x;
    if (i >= g_count) return;
    int r = g_crecv[i];
    float ev = expf(g_logits[i] - g_segmax[r]);
    g_e[i] = ev;
    atomicAdd(g_denom + r, ev);
}

// ---------------- weighted scatter-add ----------------
__global__ void aggr_kernel() {
    int w = (blockIdx.x * blockDim.x + threadIdx.x) >> 5;
    if (w >= g_count) return;
    int lane = threadIdx.x & 31;
    int r = g_crecv[w];
    float coef = g_e[w] / (g_denom[r] + 1e-9f);
    float4 mv = *(const float4*)(g_msg + (size_t)w * MSGD + lane * 4);
    float* dst = g_aggr + (size_t)r * MSGD + lane * 4;
    atomicAdd(dst + 0, coef * mv.x);
    atomicAdd(dst + 1, coef * mv.y);
    atomicAdd(dst + 2, coef * mv.z);
    atomicAdd(dst + 3, coef * mv.w);
}

// ---------------- agent MLP --------------------------------------------------
__global__ __launch_bounds__(256, 2) void agent_mlp_kernel(
    const float* __restrict__ W_h1, const float* __restrict__ b_h1,
    const float* __restrict__ W_h2, const float* __restrict__ b_h2,
    const float* __restrict__ W_out, const float* __restrict__ b_out,
    float* __restrict__ out, int n_agents)
{
    extern __shared__ float smem[];
    float (*s_x)[XPAD] = (float (*)[XPAD])smem;
    float (*s_h)[HPAD] = (float (*)[HPAD])(smem + BM * XPAD);

    const int r0 = blockIdx.x * BM;
    const int tid = threadIdx.x;

    for (int idx = tid; idx < BM * 32; idx += 256) {
        int m = idx >> 5, p = idx & 31;
        int r = r0 + m;
        float4 v = make_float4(0.f, 0.f, 0.f, 0.f);
        if (r < n_agents) v = *(const float4*)(g_aggr + (size_t)r * MSGD + p * 4);
        *(float4*)&s_x[m][p * 4] = v;
    }
    __syncthreads();

    const int tx = tid & 15, ty = tid >> 4;
    const int n0 = tx * 16, m0 = ty * 4;

    u64 acc[4][8];
    {
        const u64* bp = (const u64*)(b_h1 + n0);
        u64 bv[8];
        #pragma unroll
        for (int p = 0; p < 8; p++) bv[p] = bp[p];
        #pragma unroll
        for (int i = 0; i < 4; i++)
            #pragma unroll
            for (int p = 0; p < 8; p++) acc[i][p] = bv[p];
    }
    #pragma unroll 2
    for (int k = 0; k < MSGD; k++) {
        u64 a0 = pack2(s_x[m0 + 0][k]), a1 = pack2(s_x[m0 + 1][k]);
        u64 a2 = pack2(s_x[m0 + 2][k]), a3 = pack2(s_x[m0 + 3][k]);
        const ulonglong2* wp = (const ulonglong2*)(W_h1 + k * HID + n0);
        ulonglong2 w0 = wp[0], w1 = wp[1], w2 = wp[2], w3 = wp[3];
        u64 w[8] = {w0.x, w0.y, w1.x, w1.y, w2.x, w2.y, w3.x, w3.y};
        #pragma unroll
        for (int p = 0; p < 8; p++) {
            acc[0][p] = ffma2(a0, w[p], acc[0][p]);
            acc[1][p] = ffma2(a1, w[p], acc[1][p]);
            acc[2][p] = ffma2(a2, w[p], acc[2][p]);
            acc[3][p] = ffma2(a3, w[p], acc[3][p]);
        }
    }
    #pragma unroll
    for (int i = 0; i < 4; i++) {
        #pragma unroll
        for (int g = 0; g < 4; g++) {
            float2 u0 = unpack2(acc[i][2 * g]);
            float2 u1 = unpack2(acc[i][2 * g + 1]);
            float4 r;
            r.x = fmaxf(u0.x, 0.f); r.y = fmaxf(u0.y, 0.f);
            r.z = fmaxf(u1.x, 0.f); r.w = fmaxf(u1.y, 0.f);
            *(float4*)&s_h[m0 + i][n0 + g * 4] = r;
        }
    }
    __syncthreads();

    {
        const u64* bp = (const u64*)(b_h2 + n0);
        u64 bv[8];
        #pragma unroll
        for (int p = 0; p < 8; p++) bv[p] = bp[p];
        #pragma unroll
        for (int i = 0; i < 4; i++)
            #pragma unroll
            for (int p = 0; p < 8; p++) acc[i][p] = bv[p];
    }
    #pragma unroll 2
    for (int k = 0; k < HID; k++) {
        u64 a0 = pack2(s_h[m0 + 0][k]), a1 = pack2(s_h[m0 + 1][k]);
        u64 a2 = pack2(s_h[m0 + 2][k]), a3 = pack2(s_h[m0 + 3][k]);
        const ulonglong2* wp = (const ulonglong2*)(W_h2 + k * HID + n0);
        ulonglong2 w0 = wp[0], w1 = wp[1], w2 = wp[2], w3 = wp[3];
        u64 w[8] = {w0.x, w0.y, w1.x, w1.y, w2.x, w2.y, w3.x, w3.y};
        #pragma unroll
        for (int p = 0; p < 8; p++) {
            acc[0][p] = ffma2(a0, w[p], acc[0][p]);
            acc[1][p] = ffma2(a1, w[p], acc[1][p]);
            acc[2][p] = ffma2(a2, w[p], acc[2][p]);
            acc[3][p] = ffma2(a3, w[p], acc[3][p]);
        }
    }

    float wo[16];
    *(float4*)&wo[0]  = *(const float4*)(W_out + n0);
    *(float4*)&wo[4]  = *(const float4*)(W_out + n0 + 4);
    *(float4*)&wo[8]  = *(const float4*)(W_out + n0 + 8);
    *(float4*)&wo[12] = *(const float4*)(W_out + n0 + 12);
    float partial[4];
    #pragma unroll
    for (int i = 0; i < 4; i++) {
        float s = 0.f;
        #pragma unroll
        for (int p = 0; p < 8; p++) {
            float2 u = unpack2(acc[i][p]);
            s = fmaf(fmaxf(u.x, 0.f), wo[2 * p], s);
            s = fmaf(fmaxf(u.y, 0.f), wo[2 * p + 1], s);
        }
        partial[i] = s;
    }
    #pragma unroll
    for (int o = 8; o >= 1; o >>= 1) {
        #pragma unroll
        for (int i = 0; i < 4; i++)
            partial[i] += __shfl_xor_sync(0xffffffffu, partial[i], o);
    }
    if (tx == 0) {
        float bo = b_out[0];
        #pragma unroll
        for (int i = 0; i < 4; i++) {
            int r = r0 + m0 + i;
            if (r < n_agents) out[r] = tanhf(partial[i] + bo);
        }
    }
}

// ---------------------------------------------------------------------------
extern "C" void kernel_launch(void* const* d_in, const int* in_sizes, int n_in,
                              void* d_out, int out_size) {
    const float* node_feats = (const float*)d_in[0];
    const float* edge_feats = (const float*)d_in[1];
    const float* W_msg1 = (const float*)d_in[2];
    const float* b_msg1 = (const float*)d_in[3];
    const float* W_msg2 = (const float*)d_in[4];
    const float* b_msg2 = (const float*)d_in[5];
    const float* w_gate = (const float*)d_in[6];
    const float* b_gate = (const float*)d_in[7];
    const float* W_h1   = (const float*)d_in[8];
    const float* b_h1   = (const float*)d_in[9];
    const float* W_h2   = (const float*)d_in[10];
    const float* b_h2   = (const float*)d_in[11];
    const float* W_out  = (const float*)d_in[12];
    const float* b_out  = (const float*)d_in[13];
    const int* senders   = (const int*)d_in[14];
    const int* receivers = (const int*)d_in[15];
    float* out = (float*)d_out;

    const int n_edges  = in_sizes[14];
    const int n_nodes  = in_sizes[0] / ND;
    const int n_agents = out_size;

    const int SMEM_EDGE  = (BM * EPAD + BM * HPAD) * (int)sizeof(float) + 3 * BM * (int)sizeof(int);
    const int SMEM_AGENT = (BM * XPAD + BM * HPAD) * (int)sizeof(float);
    cudaFuncSetAttribute(edge_mlp_kernel, cudaFuncAttributeMaxDynamicSharedMemorySize, SMEM_EDGE);
    cudaFuncSetAttribute(agent_mlp_kernel, cudaFuncAttributeMaxDynamicSharedMemorySize, SMEM_AGENT);

    {
        int total = n_agents * MSGD;
        init_kernel<<<(total + 255) / 256, 256>>>(n_agents);
    }
    compact_kernel<<<(n_edges + 255) / 256, 256>>>(receivers, n_edges, n_agents);
    {
        dim3 grid((n_nodes + BM - 1) / BM, 2);
        node_proj_kernel<<<grid, 256>>>(node_feats, W_msg1, n_nodes);
    }
    {
        int grid = (n_edges + BM - 1) / BM;
        edge_mlp_kernel<<<grid, 256, SMEM_EDGE>>>(
            edge_feats, W_msg1, b_msg1, W_msg2, b_msg2, w_gate, b_gate, senders);
    }
    seg_max_kernel<<<(n_edges + 255) / 256, 256>>>();
    exp_denom_kernel<<<(n_edges + 255) / 256, 256>>>();
    {
        long long warps = n_edges;
        int grid = (int)((warps * 32 + 255) / 256);
        aggr_kernel<<<grid, 256>>>();
    }
    agent_mlp_kernel<<<(n_agents + BM - 1) / BM, 256, SMEM_AGENT>>>(
        W_h1, b_h1, W_h2, b_h2, W_out, b_out, out, n_agents);
}

// round 4
// speedup vs baseline: 1.7238x; 1.0897x over previous
#include <cuda_runtime.h>
#include <math.h>
#include <stdint.h>

#define ND   64
#define ED   32
#define HID  256
#define MSGD 128
#define MAX_EDGES 800000
#define MAX_NODES 50000

#define BM    64
#define HPAD  260     // row stride floats; *4B = 1040 (16B multiple)
#define EPAD  36      // 144 B
#define APAD  68      // 272 B
#define XPAD  132     // 528 B
#define PROJW 512     // [Ps(256) | Pr(256)] per node

typedef unsigned long long u64;

// ---- packed f32x2 helpers (sm_103a FFMA2 path) ----
__device__ __forceinline__ u64 ffma2(u64 a, u64 b, u64 c) {
    u64 d;
    asm("fma.rn.f32x2 %0, %1, %2, %3;" : "=l"(d) : "l"(a), "l"(b), "l"(c));
    return d;
}
__device__ __forceinline__ u64 pack2(float x) {
    u64 r;
    asm("mov.b64 %0, {%1, %1};" : "=l"(r) : "f"(x));
    return r;
}
__device__ __forceinline__ float2 unpack2(u64 v) {
    float2 f;
    asm("mov.b64 {%0, %1}, %2;" : "=f"(f.x), "=f"(f.y) : "l"(v));
    return f;
}
__device__ __forceinline__ void red_add_v4(float* p, float4 v) {
    asm volatile("red.global.add.v4.f32 [%0], {%1, %2, %3, %4};"
                 :: "l"(p), "f"(v.x), "f"(v.y), "f"(v.z), "f"(v.w) : "memory");
}

// ---- scratch ----
__device__ int   g_count;
__device__ int   g_active[MAX_EDGES];
__device__ int   g_crecv[MAX_EDGES];
__device__ float g_msg[(size_t)MAX_EDGES * MSGD];
__device__ float g_logits[MAX_EDGES];
__device__ float g_segmax[MAX_NODES];
__device__ float g_denom[MAX_NODES];
__device__ float g_aggr[(size_t)MAX_NODES * MSGD];
__device__ float g_proj[(size_t)MAX_NODES * PROJW];

// ---------------- init ----------------
__global__ void init_kernel(int n_agents) {
    int i = blockIdx.x * blockDim.x + threadIdx.x;
    int total = n_agents * MSGD;
    if (i < total) g_aggr[i] = 0.f;
    if (i < n_agents) { g_segmax[i] = -INFINITY; g_denom[i] = 0.f; }
    if (i == 0) g_count = 0;
}

// ---------------- compact ----------------
__global__ void compact_kernel(const int* __restrict__ recv, int n_edges, int n_agents) {
    int i = blockIdx.x * blockDim.x + threadIdx.x;
    if (i >= n_edges) return;
    int r = recv[i];
    if (r < n_agents) {
        int p = atomicAdd(&g_count, 1);
        g_active[p] = i;
        g_crecv[p]  = r;
    }
}

// ---------------- node projections: P = node_feats @ [W1_s | W1_r] ----------
// by=0: sender block, all nodes. by=1: receiver block, only nodes < n_agents.
__global__ __launch_bounds__(256, 2) void node_proj_kernel(
    const float* __restrict__ node_feats, const float* __restrict__ W1,
    int n_nodes, int n_agents)
{
    __shared__ float s_a[BM][APAD];
    const int r0 = blockIdx.x * BM;
    const int by = blockIdx.y;
    const int lim = (by == 0) ? n_nodes : n_agents;
    if (r0 >= lim) return;
    const int tid = threadIdx.x;

    for (int idx = tid; idx < BM * 16; idx += 256) {
        int m = idx >> 4, p = idx & 15;
        int row = r0 + m;
        float4 v = make_float4(0.f, 0.f, 0.f, 0.f);
        if (row < lim) v = ((const float4*)(node_feats + (size_t)row * ND))[p];
        *(float4*)&s_a[m][p * 4] = v;
    }
    __syncthreads();

    const int tx = tid & 15, ty = tid >> 4;
    const int n0 = tx * 16, m0 = ty * 4;
    const float* Wblk = W1 + (size_t)(by * 64) * HID;

    u64 acc[4][8];
    #pragma unroll
    for (int i = 0; i < 4; i++)
        #pragma unroll
        for (int p = 0; p < 8; p++) acc[i][p] = 0ull;

    for (int k = 0; k < 64; k += 4) {
        float av[4][4];
        #pragma unroll
        for (int i = 0; i < 4; i++) {
            float4 t = *(const float4*)&s_a[m0 + i][k];
            av[i][0] = t.x; av[i][1] = t.y; av[i][2] = t.z; av[i][3] = t.w;
        }
        #pragma unroll
        for (int kk = 0; kk < 4; kk++) {
            u64 a0 = pack2(av[0][kk]), a1 = pack2(av[1][kk]);
            u64 a2 = pack2(av[2][kk]), a3 = pack2(av[3][kk]);
            const ulonglong2* wp = (const ulonglong2*)(Wblk + (k + kk) * HID + n0);
            ulonglong2 w0 = wp[0], w1 = wp[1], w2 = wp[2], w3 = wp[3];
            u64 w[8] = {w0.x, w0.y, w1.x, w1.y, w2.x, w2.y, w3.x, w3.y};
            #pragma unroll
            for (int p = 0; p < 8; p++) {
                acc[0][p] = ffma2(a0, w[p], acc[0][p]);
                acc[1][p] = ffma2(a1, w[p], acc[1][p]);
                acc[2][p] = ffma2(a2, w[p], acc[2][p]);
                acc[3][p] = ffma2(a3, w[p], acc[3][p]);
            }
        }
    }
    #pragma unroll
    for (int i = 0; i < 4; i++) {
        int row = r0 + m0 + i;
        if (row < lim) {
            float* dst = g_proj + (size_t)row * PROJW + by * 256 + n0;
            #pragma unroll
            for (int g = 0; g < 4; g++) {
                float2 u0 = unpack2(acc[i][2 * g]);
                float2 u1 = unpack2(acc[i][2 * g + 1]);
                *(float4*)(dst + g * 4) = make_float4(u0.x, u0.y, u1.x, u1.y);
            }
        }
    }
}

// ---------------- fused edge MLP (+ segmax atomics) --------------------------
__global__ __launch_bounds__(256, 2) void edge_mlp_kernel(
    const float* __restrict__ edge_feats,
    const float* __restrict__ W1, const float* __restrict__ b1,
    const float* __restrict__ W2, const float* __restrict__ b2,
    const float* __restrict__ w_gate, const float* __restrict__ b_gate,
    const int* __restrict__ senders)
{
    extern __shared__ float smem[];
    float (*s_e)[EPAD] = (float (*)[EPAD])smem;                  // 64 x 36
    float (*s_h)[HPAD] = (float (*)[HPAD])(smem + BM * EPAD);    // 64 x 260
    int* s_is   = (int*)(smem + BM * EPAD + BM * HPAD);
    int* s_ir   = s_is + BM;
    int* s_eidx = s_ir + BM;

    const int cnt = g_count;
    const int e0  = blockIdx.x * BM;
    if (e0 >= cnt) return;
    const int tid = threadIdx.x;

    if (tid < BM) {
        int ci = e0 + tid;
        int e = 0, s = 0, r = 0;
        if (ci < cnt) { e = g_active[ci]; s = senders[e]; r = g_crecv[ci]; }
        s_eidx[tid] = e; s_is[tid] = s; s_ir[tid] = r;
    }
    __syncthreads();

    // pre-sum Ps + Pr into s_h + stage edge feats
    for (int idx = tid; idx < BM * 64; idx += 256) {
        int m = idx >> 6, p = idx & 63;
        const float4 a = *(const float4*)(g_proj + (size_t)s_is[m] * PROJW + p * 4);
        const float4 b = *(const float4*)(g_proj + (size_t)s_ir[m] * PROJW + 256 + p * 4);
        *(float4*)&s_h[m][p * 4] = make_float4(a.x + b.x, a.y + b.y, a.z + b.z, a.w + b.w);
    }
    for (int idx = tid; idx < BM * 8; idx += 256) {
        int m = idx >> 3, p = idx & 7;
        float4 v = make_float4(0.f, 0.f, 0.f, 0.f);
        if (e0 + m < cnt) v = ((const float4*)(edge_feats + (size_t)s_eidx[m] * ED))[p];
        *(float4*)&s_e[m][p * 4] = v;
    }
    __syncthreads();

    const int tx = tid & 15, ty = tid >> 4;
    const int n0 = tx * 16, m0 = ty * 4;

    // ---- edge-proj GEMM (K=32) + bias, packed, vectorized LDS ----
    u64 acc[4][8];
    {
        const u64* bp = (const u64*)(b1 + n0);
        u64 bv[8];
        #pragma unroll
        for (int p = 0; p < 8; p++) bv[p] = bp[p];
        #pragma unroll
        for (int i = 0; i < 4; i++)
            #pragma unroll
            for (int p = 0; p < 8; p++) acc[i][p] = bv[p];
    }
    const float* W1e = W1 + (size_t)(2 * ND) * HID;
    for (int k = 0; k < ED; k += 4) {
        float av[4][4];
        #pragma unroll
        for (int i = 0; i < 4; i++) {
            float4 t = *(const float4*)&s_e[m0 + i][k];
            av[i][0] = t.x; av[i][1] = t.y; av[i][2] = t.z; av[i][3] = t.w;
        }
        #pragma unroll
        for (int kk = 0; kk < 4; kk++) {
            u64 a0 = pack2(av[0][kk]), a1 = pack2(av[1][kk]);
            u64 a2 = pack2(av[2][kk]), a3 = pack2(av[3][kk]);
            const ulonglong2* wp = (const ulonglong2*)(W1e + (k + kk) * HID + n0);
            ulonglong2 w0 = wp[0], w1 = wp[1], w2 = wp[2], w3 = wp[3];
            u64 w[8] = {w0.x, w0.y, w1.x, w1.y, w2.x, w2.y, w3.x, w3.y};
            #pragma unroll
            for (int p = 0; p < 8; p++) {
                acc[0][p] = ffma2(a0, w[p], acc[0][p]);
                acc[1][p] = ffma2(a1, w[p], acc[1][p]);
                acc[2][p] = ffma2(a2, w[p], acc[2][p]);
                acc[3][p] = ffma2(a3, w[p], acc[3][p]);
            }
        }
    }

    // h = relu(acc + presummed projections) -> s_h
    #pragma unroll
    for (int i = 0; i < 4; i++) {
        int m = m0 + i;
        #pragma unroll
        for (int g = 0; g < 4; g++) {
            float4 hv = *(float4*)&s_h[m][n0 + g * 4];
            float2 u0 = unpack2(acc[i][2 * g]);
            float2 u1 = unpack2(acc[i][2 * g + 1]);
            float4 r;
            r.x = fmaxf(u0.x + hv.x, 0.f);
            r.y = fmaxf(u0.y + hv.y, 0.f);
            r.z = fmaxf(u1.x + hv.z, 0.f);
            r.w = fmaxf(u1.y + hv.w, 0.f);
            *(float4*)&s_h[m][n0 + g * 4] = r;
        }
    }
    __syncthreads();

    // ---- GEMM2: [64x256] @ [256x128], packed, vectorized LDS ----
    const int c0 = tx * 8;
    u64 acc2[4][4];
    {
        const u64* bp = (const u64*)(b2 + c0);
        u64 bv[4] = {bp[0], bp[1], bp[2], bp[3]};
        #pragma unroll
        for (int i = 0; i < 4; i++)
            #pragma unroll
            for (int p = 0; p < 4; p++) acc2[i][p] = bv[p];
    }
    #pragma unroll 2
    for (int k = 0; k < HID; k += 4) {
        float av[4][4];
        #pragma unroll
        for (int i = 0; i < 4; i++) {
            float4 t = *(const float4*)&s_h[m0 + i][k];
            av[i][0] = t.x; av[i][1] = t.y; av[i][2] = t.z; av[i][3] = t.w;
        }
        #pragma unroll
        for (int kk = 0; kk < 4; kk++) {
            u64 a0 = pack2(av[0][kk]), a1 = pack2(av[1][kk]);
            u64 a2 = pack2(av[2][kk]), a3 = pack2(av[3][kk]);
            const ulonglong2* wp = (const ulonglong2*)(W2 + (k + kk) * MSGD + c0);
            ulonglong2 w0 = wp[0], w1 = wp[1];
            u64 w[4] = {w0.x, w0.y, w1.x, w1.y};
            #pragma unroll
            for (int p = 0; p < 4; p++) {
                acc2[0][p] = ffma2(a0, w[p], acc2[0][p]);
                acc2[1][p] = ffma2(a1, w[p], acc2[1][p]);
                acc2[2][p] = ffma2(a2, w[p], acc2[2][p]);
                acc2[3][p] = ffma2(a3, w[p], acc2[3][p]);
            }
        }
    }

    // relu + gate partials + store msg
    float wg[8];
    *(float4*)&wg[0] = *(const float4*)(w_gate + c0);
    *(float4*)&wg[4] = *(const float4*)(w_gate + c0 + 4);
    float partial[4];
    #pragma unroll
    for (int i = 0; i < 4; i++) {
        float v[8];
        #pragma unroll
        for (int p = 0; p < 4; p++) {
            float2 u = unpack2(acc2[i][p]);
            v[2 * p]     = fmaxf(u.x, 0.f);
            v[2 * p + 1] = fmaxf(u.y, 0.f);
        }
        float s = 0.f;
        #pragma unroll
        for (int j = 0; j < 8; j++) s = fmaf(v[j], wg[j], s);
        partial[i] = s;
        int ci = e0 + m0 + i;
        if (ci < cnt) {
            float* dst = g_msg + (size_t)ci * MSGD + c0;
            *(float4*)(dst)     = make_float4(v[0], v[1], v[2], v[3]);
            *(float4*)(dst + 4) = make_float4(v[4], v[5], v[6], v[7]);
        }
    }
    #pragma unroll
    for (int o = 8; o >= 1; o >>= 1) {
        #pragma unroll
        for (int i = 0; i < 4; i++)
            partial[i] += __shfl_xor_sync(0xffffffffu, partial[i], o);
    }
    if (tx == 0) {
        float bg = b_gate[0];
        #pragma unroll
        for (int i = 0; i < 4; i++) {
            int ci = e0 + m0 + i;
            if (ci < cnt) {
                float v = partial[i] + bg;
                g_logits[ci] = v;
                int r = s_ir[m0 + i];
                if (v >= 0.f) atomicMax((int*)(g_segmax + r), __float_as_int(v));
                else          atomicMin((unsigned int*)(g_segmax + r),
                                        (unsigned int)__float_as_int(v));
            }
        }
    }
}

// ---------------- fused exp + denom + unnormalized scatter -------------------
// one warp per edge: lane0 adds denom; all lanes scatter e*msg with v4 red.
__global__ void aggr_kernel() {
    int w = (blockIdx.x * blockDim.x + threadIdx.x) >> 5;
    if (w >= g_count) return;
    int lane = threadIdx.x & 31;
    int r = g_crecv[w];
    float ev = expf(g_logits[w] - g_segmax[r]);
    if (lane == 0) atomicAdd(g_denom + r, ev);
    float4 mv = *(const float4*)(g_msg + (size_t)w * MSGD + lane * 4);
    red_add_v4(g_aggr + (size_t)r * MSGD + lane * 4,
               make_float4(ev * mv.x, ev * mv.y, ev * mv.z, ev * mv.w));
}

// ---------------- agent MLP (divides by denom on load) -----------------------
__global__ __launch_bounds__(256, 2) void agent_mlp_kernel(
    const float* __restrict__ W_h1, const float* __restrict__ b_h1,
    const float* __restrict__ W_h2, const float* __restrict__ b_h2,
    const float* __restrict__ W_out, const float* __restrict__ b_out,
    float* __restrict__ out, int n_agents)
{
    extern __shared__ float smem[];
    float (*s_x)[XPAD] = (float (*)[XPAD])smem;
    float (*s_h)[HPAD] = (float (*)[HPAD])(smem + BM * XPAD);

    const int r0 = blockIdx.x * BM;
    const int tid = threadIdx.x;

    for (int idx = tid; idx < BM * 32; idx += 256) {
        int m = idx >> 5, p = idx & 31;
        int r = r0 + m;
        float4 v = make_float4(0.f, 0.f, 0.f, 0.f);
        if (r < n_agents) {
            float inv = __frcp_rn(g_denom[r] + 1e-9f);
            v = *(const float4*)(g_aggr + (size_t)r * MSGD + p * 4);
            v.x *= inv; v.y *= inv; v.z *= inv; v.w *= inv;
        }
        *(float4*)&s_x[m][p * 4] = v;
    }
    __syncthreads();

    const int tx = tid & 15, ty = tid >> 4;
    const int n0 = tx * 16, m0 = ty * 4;

    u64 acc[4][8];
    {
        const u64* bp = (const u64*)(b_h1 + n0);
        u64 bv[8];
        #pragma unroll
        for (int p = 0; p < 8; p++) bv[p] = bp[p];
        #pragma unroll
        for (int i = 0; i < 4; i++)
            #pragma unroll
            for (int p = 0; p < 8; p++) acc[i][p] = bv[p];
    }
    for (int k = 0; k < MSGD; k += 4) {
        float av[4][4];
        #pragma unroll
        for (int i = 0; i < 4; i++) {
            float4 t = *(const float4*)&s_x[m0 + i][k];
            av[i][0] = t.x; av[i][1] = t.y; av[i][2] = t.z; av[i][3] = t.w;
        }
        #pragma unroll
        for (int kk = 0; kk < 4; kk++) {
            u64 a0 = pack2(av[0][kk]), a1 = pack2(av[1][kk]);
            u64 a2 = pack2(av[2][kk]), a3 = pack2(av[3][kk]);
            const ulonglong2* wp = (const ulonglong2*)(W_h1 + (k + kk) * HID + n0);
            ulonglong2 w0 = wp[0], w1 = wp[1], w2 = wp[2], w3 = wp[3];
            u64 w[8] = {w0.x, w0.y, w1.x, w1.y, w2.x, w2.y, w3.x, w3.y};
            #pragma unroll
            for (int p = 0; p < 8; p++) {
                acc[0][p] = ffma2(a0, w[p], acc[0][p]);
                acc[1][p] = ffma2(a1, w[p], acc[1][p]);
                acc[2][p] = ffma2(a2, w[p], acc[2][p]);
                acc[3][p] = ffma2(a3, w[p], acc[3][p]);
            }
        }
    }
    #pragma unroll
    for (int i = 0; i < 4; i++) {
        #pragma unroll
        for (int g = 0; g < 4; g++) {
            float2 u0 = unpack2(acc[i][2 * g]);
            float2 u1 = unpack2(acc[i][2 * g + 1]);
            float4 r;
            r.x = fmaxf(u0.x, 0.f); r.y = fmaxf(u0.y, 0.f);
            r.z = fmaxf(u1.x, 0.f); r.w = fmaxf(u1.y, 0.f);
            *(float4*)&s_h[m0 + i][n0 + g * 4] = r;
        }
    }
    __syncthreads();

    {
        const u64* bp = (const u64*)(b_h2 + n0);
        u64 bv[8];
        #pragma unroll
        for (int p = 0; p < 8; p++) bv[p] = bp[p];
        #pragma unroll
        for (int i = 0; i < 4; i++)
            #pragma unroll
            for (int p = 0; p < 8; p++) acc[i][p] = bv[p];
    }
    #pragma unroll 2
    for (int k = 0; k < HID; k += 4) {
        float av[4][4];
        #pragma unroll
        for (int i = 0; i < 4; i++) {
            float4 t = *(const float4*)&s_h[m0 + i][k];
            av[i][0] = t.x; av[i][1] = t.y; av[i][2] = t.z; av[i][3] = t.w;
        }
        #pragma unroll
        for (int kk = 0; kk < 4; kk++) {
            u64 a0 = pack2(av[0][kk]), a1 = pack2(av[1][kk]);
            u64 a2 = pack2(av[2][kk]), a3 = pack2(av[3][kk]);
            const ulonglong2* wp = (const ulonglong2*)(W_h2 + (k + kk) * HID + n0);
            ulonglong2 w0 = wp[0], w1 = wp[1], w2 = wp[2], w3 = wp[3];
            u64 w[8] = {w0.x, w0.y, w1.x, w1.y, w2.x, w2.y, w3.x, w3.y};
            #pragma unroll
            for (int p = 0; p < 8; p++) {
                acc[0][p] = ffma2(a0, w[p], acc[0][p]);
                acc[1][p] = ffma2(a1, w[p], acc[1][p]);
                acc[2][p] = ffma2(a2, w[p], acc[2][p]);
                acc[3][p] = ffma2(a3, w[p], acc[3][p]);
            }
        }
    }

    float wo[16];
    *(float4*)&wo[0]  = *(const float4*)(W_out + n0);
    *(float4*)&wo[4]  = *(const float4*)(W_out + n0 + 4);
    *(float4*)&wo[8]  = *(const float4*)(W_out + n0 + 8);
    *(float4*)&wo[12] = *(const float4*)(W_out + n0 + 12);
    float partial[4];
    #pragma unroll
    for (int i = 0; i < 4; i++) {
        float s = 0.f;
        #pragma unroll
        for (int p = 0; p < 8; p++) {
            float2 u = unpack2(acc[i][p]);
            s = fmaf(fmaxf(u.x, 0.f), wo[2 * p], s);
            s = fmaf(fmaxf(u.y, 0.f), wo[2 * p + 1], s);
        }
        partial[i] = s;
    }
    #pragma unroll
    for (int o = 8; o >= 1; o >>= 1) {
        #pragma unroll
        for (int i = 0; i < 4; i++)
            partial[i] += __shfl_xor_sync(0xffffffffu, partial[i], o);
    }
    if (tx == 0) {
        float bo = b_out[0];
        #pragma unroll
        for (int i = 0; i < 4; i++) {
            int r = r0 + m0 + i;
            if (r < n_agents) out[r] = tanhf(partial[i] + bo);
        }
    }
}

// ---------------------------------------------------------------------------
extern "C" void kernel_launch(void* const* d_in, const int* in_sizes, int n_in,
                              void* d_out, int out_size) {
    const float* node_feats = (const float*)d_in[0];
    const float* edge_feats = (const float*)d_in[1];
    const float* W_msg1 = (const float*)d_in[2];
    const float* b_msg1 = (const float*)d_in[3];
    const float* W_msg2 = (const float*)d_in[4];
    const float* b_msg2 = (const float*)d_in[5];
    const float* w_gate = (const float*)d_in[6];
    const float* b_gate = (const float*)d_in[7];
    const float* W_h1   = (const float*)d_in[8];
    const float* b_h1   = (const float*)d_in[9];
    const float* W_h2   = (const float*)d_in[10];
    const float* b_h2   = (const float*)d_in[11];
    const float* W_out  = (const float*)d_in[12];
    const float* b_out  = (const float*)d_in[13];
    const int* senders   = (const int*)d_in[14];
    const int* receivers = (const int*)d_in[15];
    float* out = (float*)d_out;

    const int n_edges  = in_sizes[14];
    const int n_nodes  = in_sizes[0] / ND;
    const int n_agents = out_size;

    const int SMEM_EDGE  = (BM * EPAD + BM * HPAD) * (int)sizeof(float) + 3 * BM * (int)sizeof(int);
    const int SMEM_AGENT = (BM * XPAD + BM * HPAD) * (int)sizeof(float);
    cudaFuncSetAttribute(edge_mlp_kernel, cudaFuncAttributeMaxDynamicSharedMemorySize, SMEM_EDGE);
    cudaFuncSetAttribute(agent_mlp_kernel, cudaFuncAttributeMaxDynamicSharedMemorySize, SMEM_AGENT);

    {
        int total = n_agents * MSGD;
        init_kernel<<<(total + 255) / 256, 256>>>(n_agents);
    }
    compact_kernel<<<(n_edges + 255) / 256, 256>>>(receivers, n_edges, n_agents);
    {
        dim3 grid((n_nodes + BM - 1) / BM, 2);
        node_proj_kernel<<<grid, 256>>>(node_feats, W_msg1, n_nodes, n_agents);
    }
    {
        int grid = (n_edges + BM - 1) / BM;
        edge_mlp_kernel<<<grid, 256, SMEM_EDGE>>>(
            edge_feats, W_msg1, b_msg1, W_msg2, b_msg2, w_gate, b_gate, senders);
    }
    {
        long long warps = n_edges;
        int grid = (int)((warps * 32 + 255) / 256);
        aggr_kernel<<<grid, 256>>>();
    }
    agent_mlp_kernel<<<(n_agents + BM - 1) / BM, 256, SMEM_AGENT>>>(
        W_h1, b_h1, W_h2, b_h2, W_out, b_out, out, n_agents);
}

// round 5
// speedup vs baseline: 2.7999x; 1.6242x over previous
#include <cuda_runtime.h>
#include <math.h>
#include <stdint.h>

#define ND   64
#define ED   32
#define HID  256
#define MSGD 128
#define MAX_EDGES 800000
#define MAX_NODES 50000

#define BM    64
#define HPAD  260     // row stride floats; *4B = 1040 (16B multiple)
#define EPAD  36
#define APAD  68
#define XPAD  132
#define PROJW 512     // [Ps(256) | Pr(256)] per node

typedef unsigned long long u64;

// ---- packed f32x2 helpers (sm_103a FFMA2 path) ----
__device__ __forceinline__ u64 ffma2(u64 a, u64 b, u64 c) {
    u64 d;
    asm("fma.rn.f32x2 %0, %1, %2, %3;" : "=l"(d) : "l"(a), "l"(b), "l"(c));
    return d;
}
__device__ __forceinline__ u64 pack2(float x) {
    u64 r;
    asm("mov.b64 %0, {%1, %1};" : "=l"(r) : "f"(x));
    return r;
}
__device__ __forceinline__ float2 unpack2(u64 v) {
    float2 f;
    asm("mov.b64 {%0, %1}, %2;" : "=f"(f.x), "=f"(f.y) : "l"(v));
    return f;
}
__device__ __forceinline__ void red_add_v4(float* p, float4 v) {
    asm volatile("red.global.add.v4.f32 [%0], {%1, %2, %3, %4};"
                 :: "l"(p), "f"(v.x), "f"(v.y), "f"(v.z), "f"(v.w) : "memory");
}

// ---- scratch ----
__device__ int   g_count;
__device__ int   g_active[MAX_EDGES];
__device__ int   g_crecv[MAX_EDGES];
__device__ float g_msg[(size_t)MAX_EDGES * MSGD];
__device__ float g_logits[MAX_EDGES];
__device__ float g_segmax[MAX_NODES];
__device__ float g_denom[MAX_NODES];
__device__ float g_aggr[(size_t)MAX_NODES * MSGD];
__device__ float g_proj[(size_t)MAX_NODES * PROJW];

// ---------------- init ----------------
__global__ void init_kernel(int n_agents) {
    int i = blockIdx.x * blockDim.x + threadIdx.x;
    int total = n_agents * MSGD;
    if (i < total) g_aggr[i] = 0.f;
    if (i < n_agents) { g_segmax[i] = -INFINITY; g_denom[i] = 0.f; }
    if (i == 0) g_count = 0;
}

// ---------------- compact ----------------
__global__ void compact_kernel(const int* __restrict__ recv, int n_edges, int n_agents) {
    int i = blockIdx.x * blockDim.x + threadIdx.x;
    if (i >= n_edges) return;
    int r = recv[i];
    if (r < n_agents) {
        int p = atomicAdd(&g_count, 1);
        g_active[p] = i;
        g_crecv[p]  = r;
    }
}

// ---------------- node projections: P = node_feats @ [W1_s | W1_r] ----------
__global__ __launch_bounds__(256, 2) void node_proj_kernel(
    const float* __restrict__ node_feats, const float* __restrict__ W1,
    int n_nodes, int n_agents)
{
    __shared__ float s_a[BM][APAD];
    const int r0 = blockIdx.x * BM;
    const int by = blockIdx.y;
    const int lim = (by == 0) ? n_nodes : n_agents;
    if (r0 >= lim) return;
    const int tid = threadIdx.x;

    for (int idx = tid; idx < BM * 16; idx += 256) {
        int m = idx >> 4, p = idx & 15;
        int row = r0 + m;
        float4 v = make_float4(0.f, 0.f, 0.f, 0.f);
        if (row < lim) v = ((const float4*)(node_feats + (size_t)row * ND))[p];
        *(float4*)&s_a[m][p * 4] = v;
    }
    __syncthreads();

    // 32 lanes x 8 warps; per-thread 8 rows x 8 cols
    const int tx = tid & 31, ty = tid >> 5;
    const int n0 = tx * 8, m0 = ty * 8;
    const float* Wblk = W1 + (size_t)(by * 64) * HID;

    u64 acc[8][4];
    #pragma unroll
    for (int i = 0; i < 8; i++)
        #pragma unroll
        for (int p = 0; p < 4; p++) acc[i][p] = 0ull;

    for (int k = 0; k < 64; k += 4) {
        float av[8][4];
        #pragma unroll
        for (int i = 0; i < 8; i++)
            *(float4*)av[i] = *(const float4*)&s_a[m0 + i][k];
        #pragma unroll
        for (int kk = 0; kk < 4; kk++) {
            const ulonglong2* wp = (const ulonglong2*)(Wblk + (k + kk) * HID + n0);
            ulonglong2 w01 = wp[0], w23 = wp[1];
            u64 w[4] = {w01.x, w01.y, w23.x, w23.y};
            #pragma unroll
            for (int i = 0; i < 8; i++) {
                u64 a = pack2(av[i][kk]);
                #pragma unroll
                for (int p = 0; p < 4; p++) acc[i][p] = ffma2(a, w[p], acc[i][p]);
            }
        }
    }
    #pragma unroll
    for (int i = 0; i < 8; i++) {
        int row = r0 + m0 + i;
        if (row < lim) {
            float* dst = g_proj + (size_t)row * PROJW + by * 256 + n0;
            #pragma unroll
            for (int g = 0; g < 2; g++) {
                float2 u0 = unpack2(acc[i][2 * g]);
                float2 u1 = unpack2(acc[i][2 * g + 1]);
                *(float4*)(dst + g * 4) = make_float4(u0.x, u0.y, u1.x, u1.y);
            }
        }
    }
}

// ---------------- fused edge MLP (+ segmax atomics) --------------------------
// 256 threads = 8 warps x 32 lanes; per-thread: GEMM1 8x8, GEMM2 8x4
__global__ __launch_bounds__(256, 2) void edge_mlp_kernel(
    const float* __restrict__ edge_feats,
    const float* __restrict__ W1, const float* __restrict__ b1,
    const float* __restrict__ W2, const float* __restrict__ b2,
    const float* __restrict__ w_gate, const float* __restrict__ b_gate,
    const int* __restrict__ senders)
{
    extern __shared__ float smem[];
    float (*s_e)[EPAD] = (float (*)[EPAD])smem;                  // 64 x 36
    float (*s_h)[HPAD] = (float (*)[HPAD])(smem + BM * EPAD);    // 64 x 260
    int* s_is   = (int*)(smem + BM * EPAD + BM * HPAD);
    int* s_ir   = s_is + BM;
    int* s_eidx = s_ir + BM;

    const int cnt = g_count;
    const int e0  = blockIdx.x * BM;
    if (e0 >= cnt) return;
    const int tid = threadIdx.x;

    if (tid < BM) {
        int ci = e0 + tid;
        int e = 0, s = 0, r = 0;
        if (ci < cnt) { e = g_active[ci]; s = senders[e]; r = g_crecv[ci]; }
        s_eidx[tid] = e; s_is[tid] = s; s_ir[tid] = r;
    }
    __syncthreads();

    // pre-sum Ps + Pr into s_h + stage edge feats
    for (int idx = tid; idx < BM * 64; idx += 256) {
        int m = idx >> 6, p = idx & 63;
        const float4 a = *(const float4*)(g_proj + (size_t)s_is[m] * PROJW + p * 4);
        const float4 b = *(const float4*)(g_proj + (size_t)s_ir[m] * PROJW + 256 + p * 4);
        *(float4*)&s_h[m][p * 4] = make_float4(a.x + b.x, a.y + b.y, a.z + b.z, a.w + b.w);
    }
    for (int idx = tid; idx < BM * 8; idx += 256) {
        int m = idx >> 3, p = idx & 7;
        float4 v = make_float4(0.f, 0.f, 0.f, 0.f);
        if (e0 + m < cnt) v = ((const float4*)(edge_feats + (size_t)s_eidx[m] * ED))[p];
        *(float4*)&s_e[m][p * 4] = v;
    }
    __syncthreads();

    const int tx = tid & 31, ty = tid >> 5;
    const int n0 = tx * 8, m0 = ty * 8;

    // ---- GEMM1 (edge part, K=32) + bias: per-thread 8 rows x 8 cols ----
    u64 acc[8][4];
    {
        const u64* bp = (const u64*)(b1 + n0);
        u64 bv[4] = {bp[0], bp[1], bp[2], bp[3]};
        #pragma unroll
        for (int i = 0; i < 8; i++)
            #pragma unroll
            for (int p = 0; p < 4; p++) acc[i][p] = bv[p];
    }
    const float* W1e = W1 + (size_t)(2 * ND) * HID;
    for (int k = 0; k < ED; k += 4) {
        float av[8][4];
        #pragma unroll
        for (int i = 0; i < 8; i++)
            *(float4*)av[i] = *(const float4*)&s_e[m0 + i][k];
        #pragma unroll
        for (int kk = 0; kk < 4; kk++) {
            const ulonglong2* wp = (const ulonglong2*)(W1e + (k + kk) * HID + n0);
            ulonglong2 w01 = wp[0], w23 = wp[1];
            u64 w[4] = {w01.x, w01.y, w23.x, w23.y};
            #pragma unroll
            for (int i = 0; i < 8; i++) {
                u64 a = pack2(av[i][kk]);
                #pragma unroll
                for (int p = 0; p < 4; p++) acc[i][p] = ffma2(a, w[p], acc[i][p]);
            }
        }
    }

    // h = relu(acc + presummed projections) -> s_h
    #pragma unroll
    for (int i = 0; i < 8; i++) {
        int m = m0 + i;
        #pragma unroll
        for (int g = 0; g < 2; g++) {
            float4 hv = *(float4*)&s_h[m][n0 + g * 4];
            float2 u0 = unpack2(acc[i][2 * g]);
            float2 u1 = unpack2(acc[i][2 * g + 1]);
            float4 r;
            r.x = fmaxf(u0.x + hv.x, 0.f);
            r.y = fmaxf(u0.y + hv.y, 0.f);
            r.z = fmaxf(u1.x + hv.z, 0.f);
            r.w = fmaxf(u1.y + hv.w, 0.f);
            *(float4*)&s_h[m][n0 + g * 4] = r;
        }
    }
    __syncthreads();

    // ---- GEMM2: [64x256] @ [256x128]: per-thread 8 rows x 4 cols ----
    const int c0 = tx * 4;
    u64 acc2[8][2];
    {
        const u64* bp = (const u64*)(b2 + c0);
        u64 b0 = bp[0], b1v = bp[1];
        #pragma unroll
        for (int i = 0; i < 8; i++) { acc2[i][0] = b0; acc2[i][1] = b1v; }
    }
    #pragma unroll 2
    for (int k = 0; k < HID; k += 4) {
        float av[8][4];
        #pragma unroll
        for (int i = 0; i < 8; i++)
            *(float4*)av[i] = *(const float4*)&s_h[m0 + i][k];
        #pragma unroll
        for (int kk = 0; kk < 4; kk++) {
            const ulonglong2* wp = (const ulonglong2*)(W2 + (k + kk) * MSGD + c0);
            ulonglong2 w01 = *wp;
            #pragma unroll
            for (int i = 0; i < 8; i++) {
                u64 a = pack2(av[i][kk]);
                acc2[i][0] = ffma2(a, w01.x, acc2[i][0]);
                acc2[i][1] = ffma2(a, w01.y, acc2[i][1]);
            }
        }
    }

    // relu + gate partials + store msg
    float wg[4];
    *(float4*)wg = *(const float4*)(w_gate + c0);
    float partial[8];
    #pragma unroll
    for (int i = 0; i < 8; i++) {
        float2 u0 = unpack2(acc2[i][0]);
        float2 u1 = unpack2(acc2[i][1]);
        float v0 = fmaxf(u0.x, 0.f), v1 = fmaxf(u0.y, 0.f);
        float v2 = fmaxf(u1.x, 0.f), v3 = fmaxf(u1.y, 0.f);
        float s = v0 * wg[0];
        s = fmaf(v1, wg[1], s);
        s = fmaf(v2, wg[2], s);
        s = fmaf(v3, wg[3], s);
        partial[i] = s;
        int ci = e0 + m0 + i;
        if (ci < cnt)
            *(float4*)(g_msg + (size_t)ci * MSGD + c0) = make_float4(v0, v1, v2, v3);
    }
    #pragma unroll
    for (int o = 16; o >= 1; o >>= 1) {
        #pragma unroll
        for (int i = 0; i < 8; i++)
            partial[i] += __shfl_xor_sync(0xffffffffu, partial[i], o);
    }
    if (tx == 0) {
        float bg = b_gate[0];
        #pragma unroll
        for (int i = 0; i < 8; i++) {
            int ci = e0 + m0 + i;
            if (ci < cnt) {
                float v = partial[i] + bg;
                g_logits[ci] = v;
                int r = s_ir[m0 + i];
                if (v >= 0.f) atomicMax((int*)(g_segmax + r), __float_as_int(v));
                else          atomicMin((unsigned int*)(g_segmax + r),
                                        (unsigned int)__float_as_int(v));
            }
        }
    }
}

// ---------------- fused exp + denom + unnormalized scatter -------------------
__global__ void aggr_kernel() {
    int w = (blockIdx.x * blockDim.x + threadIdx.x) >> 5;
    if (w >= g_count) return;
    int lane = threadIdx.x & 31;
    int r = g_crecv[w];
    float ev = expf(g_logits[w] - g_segmax[r]);
    if (lane == 0) atomicAdd(g_denom + r, ev);
    float4 mv = *(const float4*)(g_msg + (size_t)w * MSGD + lane * 4);
    red_add_v4(g_aggr + (size_t)r * MSGD + lane * 4,
               make_float4(ev * mv.x, ev * mv.y, ev * mv.z, ev * mv.w));
}

// ---------------- agent MLP (divides by denom on load) -----------------------
__global__ __launch_bounds__(256, 2) void agent_mlp_kernel(
    const float* __restrict__ W_h1, const float* __restrict__ b_h1,
    const float* __restrict__ W_h2, const float* __restrict__ b_h2,
    const float* __restrict__ W_out, const float* __restrict__ b_out,
    float* __restrict__ out, int n_agents)
{
    extern __shared__ float smem[];
    float (*s_x)[XPAD] = (float (*)[XPAD])smem;
    float (*s_h)[HPAD] = (float (*)[HPAD])(smem + BM * XPAD);

    const int r0 = blockIdx.x * BM;
    const int tid = threadIdx.x;

    for (int idx = tid; idx < BM * 32; idx += 256) {
        int m = idx >> 5, p = idx & 31;
        int r = r0 + m;
        float4 v = make_float4(0.f, 0.f, 0.f, 0.f);
        if (r < n_agents) {
            float inv = __frcp_rn(g_denom[r] + 1e-9f);
            v = *(const float4*)(g_aggr + (size_t)r * MSGD + p * 4);
            v.x *= inv; v.y *= inv; v.z *= inv; v.w *= inv;
        }
        *(float4*)&s_x[m][p * 4] = v;
    }
    __syncthreads();

    // 32 lanes x 8 warps; per-thread 8 rows x 8 cols
    const int tx = tid & 31, ty = tid >> 5;
    const int n0 = tx * 8, m0 = ty * 8;

    u64 acc[8][4];
    {
        const u64* bp = (const u64*)(b_h1 + n0);
        u64 bv[4] = {bp[0], bp[1], bp[2], bp[3]};
        #pragma unroll
        for (int i = 0; i < 8; i++)
            #pragma unroll
            for (int p = 0; p < 4; p++) acc[i][p] = bv[p];
    }
    for (int k = 0; k < MSGD; k += 4) {
        float av[8][4];
        #pragma unroll
        for (int i = 0; i < 8; i++)
            *(float4*)av[i] = *(const float4*)&s_x[m0 + i][k];
        #pragma unroll
        for (int kk = 0; kk < 4; kk++) {
            const ulonglong2* wp = (const ulonglong2*)(W_h1 + (k + kk) * HID + n0);
            ulonglong2 w01 = wp[0], w23 = wp[1];
            u64 w[4] = {w01.x, w01.y, w23.x, w23.y};
            #pragma unroll
            for (int i = 0; i < 8; i++) {
                u64 a = pack2(av[i][kk]);
                #pragma unroll
                for (int p = 0; p < 4; p++) acc[i][p] = ffma2(a, w[p], acc[i][p]);
            }
        }
    }
    #pragma unroll
    for (int i = 0; i < 8; i++) {
        #pragma unroll
        for (int g = 0; g < 2; g++) {
            float2 u0 = unpack2(acc[i][2 * g]);
            float2 u1 = unpack2(acc[i][2 * g + 1]);
            float4 r;
            r.x = fmaxf(u0.x, 0.f); r.y = fmaxf(u0.y, 0.f);
            r.z = fmaxf(u1.x, 0.f); r.w = fmaxf(u1.y, 0.f);
            *(float4*)&s_h[m0 + i][n0 + g * 4] = r;
        }
    }
    __syncthreads();

    {
        const u64* bp = (const u64*)(b_h2 + n0);
        u64 bv[4] = {bp[0], bp[1], bp[2], bp[3]};
        #pragma unroll
        for (int i = 0; i < 8; i++)
            #pragma unroll
            for (int p = 0; p < 4; p++) acc[i][p] = bv[p];
    }
    #pragma unroll 2
    for (int k = 0; k < HID; k += 4) {
        float av[8][4];
        #pragma unroll
        for (int i = 0; i < 8; i++)
            *(float4*)av[i] = *(const float4*)&s_h[m0 + i][k];
        #pragma unroll
        for (int kk = 0; kk < 4; kk++) {
            const ulonglong2* wp = (const ulonglong2*)(W_h2 + (k + kk) * HID + n0);
            ulonglong2 w01 = wp[0], w23 = wp[1];
            u64 w[4] = {w01.x, w01.y, w23.x, w23.y};
            #pragma unroll
            for (int i = 0; i < 8; i++) {
                u64 a = pack2(av[i][kk]);
                #pragma unroll
                for (int p = 0; p < 4; p++) acc[i][p] = ffma2(a, w[p], acc[i][p]);
            }
        }
    }

    float wo[8];
    *(float4*)&wo[0] = *(const float4*)(W_out + n0);
    *(float4*)&wo[4] = *(const float4*)(W_out + n0 + 4);
    float partial[8];
    #pragma unroll
    for (int i = 0; i < 8; i++) {
        float s = 0.f;
        #pragma unroll
        for (int p = 0; p < 4; p++) {
            float2 u = unpack2(acc[i][p]);
            s = fmaf(fmaxf(u.x, 0.f), wo[2 * p], s);
            s = fmaf(fmaxf(u.y, 0.f), wo[2 * p + 1], s);
        }
        partial[i] = s;
    }
    #pragma unroll
    for (int o = 16; o >= 1; o >>= 1) {
        #pragma unroll
        for (int i = 0; i < 8; i++)
            partial[i] += __shfl_xor_sync(0xffffffffu, partial[i], o);
    }
    if (tx == 0) {
        float bo = b_out[0];
        #pragma unroll
        for (int i = 0; i < 8; i++) {
            int r = r0 + m0 + i;
            if (r < n_agents) out[r] = tanhf(partial[i] + bo);
        }
    }
}

// ---------------------------------------------------------------------------
extern "C" void kernel_launch(void* const* d_in, const int* in_sizes, int n_in,
                              void* d_out, int out_size) {
    const float* node_feats = (const float*)d_in[0];
    const float* edge_feats = (const float*)d_in[1];
    const float* W_msg1 = (const float*)d_in[2];
    const float* b_msg1 = (const float*)d_in[3];
    const float* W_msg2 = (const float*)d_in[4];
    const float* b_msg2 = (const float*)d_in[5];
    const float* w_gate = (const float*)d_in[6];
    const float* b_gate = (const float*)d_in[7];
    const float* W_h1   = (const float*)d_in[8];
    const float* b_h1   = (const float*)d_in[9];
    const float* W_h2   = (const float*)d_in[10];
    const float* b_h2   = (const float*)d_in[11];
    const float* W_out  = (const float*)d_in[12];
    const float* b_out  = (const float*)d_in[13];
    const int* senders   = (const int*)d_in[14];
    const int* receivers = (const int*)d_in[15];
    float* out = (float*)d_out;

    const int n_edges  = in_sizes[14];
    const int n_nodes  = in_sizes[0] / ND;
    const int n_agents = out_size;

    const int SMEM_EDGE  = (BM * EPAD + BM * HPAD) * (int)sizeof(float) + 3 * BM * (int)sizeof(int);
    const int SMEM_AGENT = (BM * XPAD + BM * HPAD) * (int)sizeof(float);
    cudaFuncSetAttribute(edge_mlp_kernel, cudaFuncAttributeMaxDynamicSharedMemorySize, SMEM_EDGE);
    cudaFuncSetAttribute(agent_mlp_kernel, cudaFuncAttributeMaxDynamicSharedMemorySize, SMEM_AGENT);

    {
        int total = n_agents * MSGD;
        init_kernel<<<(total + 255) / 256, 256>>>(n_agents);
    }
    compact_kernel<<<(n_edges + 255) / 256, 256>>>(receivers, n_edges, n_agents);
    {
        dim3 grid((n_nodes + BM - 1) / BM, 2);
        node_proj_kernel<<<grid, 256>>>(node_feats, W_msg1, n_nodes, n_agents);
    }
    {
        int grid = (n_edges + BM - 1) / BM;
        edge_mlp_kernel<<<grid, 256, SMEM_EDGE>>>(
            edge_feats, W_msg1, b_msg1, W_msg2, b_msg2, w_gate, b_gate, senders);
    }
    {
        long long warps = n_edges;
        int grid = (int)((warps * 32 + 255) / 256);
        aggr_kernel<<<grid, 256>>>();
    }
    agent_mlp_kernel<<<(n_agents + BM - 1) / BM, 256, SMEM_AGENT>>>(
        W_h1, b_h1, W_h2, b_h2, W_out, b_out, out, n_agents);
}

// round 7
// speedup vs baseline: 2.9651x; 1.0590x over previous
#include <cuda_runtime.h>
#include <math.h>
#include <stdint.h>

#define ND   64
#define ED   32
#define HID  256
#define MSGD 128
#define MAX_EDGES 800000
#define MAX_NODES 50000

#define BM    64      // node_proj / agent tile
#define EBM   128     // edge kernel tile (512 threads)
#define HPAD  260     // *4B = 1040, 16B multiple
#define EPAD  36
#define APAD  68
#define XPAD  132
#define PROJW 512     // [Ps(256) | Pr(256)] per node

typedef unsigned long long u64;

// ---- packed f32x2 helpers (sm_103a FFMA2 path) ----
__device__ __forceinline__ u64 ffma2(u64 a, u64 b, u64 c) {
    u64 d;
    asm("fma.rn.f32x2 %0, %1, %2, %3;" : "=l"(d) : "l"(a), "l"(b), "l"(c));
    return d;
}
__device__ __forceinline__ u64 pack2(float x) {
    u64 r;
    asm("mov.b64 %0, {%1, %1};" : "=l"(r) : "f"(x));
    return r;
}
__device__ __forceinline__ float2 unpack2(u64 v) {
    float2 f;
    asm("mov.b64 {%0, %1}, %2;" : "=f"(f.x), "=f"(f.y) : "l"(v));
    return f;
}
__device__ __forceinline__ void red_add_v4(float* p, float4 v) {
    asm volatile("red.global.add.v4.f32 [%0], {%1, %2, %3, %4};"
                 :: "l"(p), "f"(v.x), "f"(v.y), "f"(v.z), "f"(v.w) : "memory");
}

// ---- scratch ----
__device__ int   g_count;
__device__ int   g_active[MAX_EDGES];
__device__ int   g_crecv[MAX_EDGES];
__device__ float g_denom[MAX_NODES];
__device__ float g_aggr[(size_t)MAX_NODES * MSGD];
__device__ float g_proj[(size_t)MAX_NODES * PROJW];

// ---------------- init ----------------
__global__ void init_kernel(int n_agents) {
    int i = blockIdx.x * blockDim.x + threadIdx.x;
    int total = n_agents * MSGD;
    if (i < total) g_aggr[i] = 0.f;
    if (i < n_agents) g_denom[i] = 0.f;
    if (i == 0) g_count = 0;
}

// ---------------- compact ----------------
__global__ void compact_kernel(const int* __restrict__ recv, int n_edges, int n_agents) {
    int i = blockIdx.x * blockDim.x + threadIdx.x;
    if (i >= n_edges) return;
    int r = recv[i];
    if (r < n_agents) {
        int p = atomicAdd(&g_count, 1);
        g_active[p] = i;
        g_crecv[p]  = r;
    }
}

// ---------------- node projections: P = node_feats @ [W1_s | W1_r] ----------
__global__ __launch_bounds__(256, 2) void node_proj_kernel(
    const float* __restrict__ node_feats, const float* __restrict__ W1,
    int n_nodes, int n_agents)
{
    __shared__ float s_a[BM][APAD];
    const int r0 = blockIdx.x * BM;
    const int by = blockIdx.y;
    const int lim = (by == 0) ? n_nodes : n_agents;
    if (r0 >= lim) return;
    const int tid = threadIdx.x;

    for (int idx = tid; idx < BM * 16; idx += 256) {
        int m = idx >> 4, p = idx & 15;
        int row = r0 + m;
        float4 v = make_float4(0.f, 0.f, 0.f, 0.f);
        if (row < lim) v = ((const float4*)(node_feats + (size_t)row * ND))[p];
        *(float4*)&s_a[m][p * 4] = v;
    }
    __syncthreads();

    const int tx = tid & 31, ty = tid >> 5;
    const int n0 = tx * 8, m0 = ty * 8;
    const float* Wblk = W1 + (size_t)(by * 64) * HID;

    u64 acc[8][4];
    #pragma unroll
    for (int i = 0; i < 8; i++)
        #pragma unroll
        for (int p = 0; p < 4; p++) acc[i][p] = 0ull;

    for (int k = 0; k < 64; k += 4) {
        float av[8][4];
        #pragma unroll
        for (int i = 0; i < 8; i++)
            *(float4*)av[i] = *(const float4*)&s_a[m0 + i][k];
        #pragma unroll
        for (int kk = 0; kk < 4; kk++) {
            const ulonglong2* wp = (const ulonglong2*)(Wblk + (k + kk) * HID + n0);
            ulonglong2 w01 = wp[0], w23 = wp[1];
            u64 w[4] = {w01.x, w01.y, w23.x, w23.y};
            #pragma unroll
            for (int i = 0; i < 8; i++) {
                u64 a = pack2(av[i][kk]);
                #pragma unroll
                for (int p = 0; p < 4; p++) acc[i][p] = ffma2(a, w[p], acc[i][p]);
            }
        }
    }
    #pragma unroll
    for (int i = 0; i < 8; i++) {
        int row = r0 + m0 + i;
        if (row < lim) {
            float* dst = g_proj + (size_t)row * PROJW + by * 256 + n0;
            #pragma unroll
            for (int g = 0; g < 2; g++) {
                float2 u0 = unpack2(acc[i][2 * g]);
                float2 u1 = unpack2(acc[i][2 * g + 1]);
                *(float4*)(dst + g * 4) = make_float4(u0.x, u0.y, u1.x, u1.y);
            }
        }
    }
}

// ---------------- fused edge MLP + softmax-free scatter ----------------------
// 512 threads = 16 warps x 32 lanes; tile = 128 edges.
// Epilogue: attn = exp(logit)/sum  ==  max-free softmax (logits are O(1)),
// each warp scatters exp(l)*msg straight from registers via red.global.v4.
__global__ __launch_bounds__(512, 1) void edge_mlp_kernel(
    const float* __restrict__ edge_feats,
    const float* __restrict__ W1, const float* __restrict__ b1,
    const float* __restrict__ W2, const float* __restrict__ b2,
    const float* __restrict__ w_gate, const float* __restrict__ b_gate,
    const int* __restrict__ senders)
{
    extern __shared__ float smem[];
    float (*s_e)[EPAD] = (float (*)[EPAD])smem;                   // 128 x 36
    float (*s_h)[HPAD] = (float (*)[HPAD])(smem + EBM * EPAD);    // 128 x 260
    int* s_is   = (int*)(smem + EBM * EPAD + EBM * HPAD);
    int* s_ir   = s_is + EBM;
    int* s_eidx = s_ir + EBM;

    const int cnt = g_count;
    const int e0  = blockIdx.x * EBM;
    if (e0 >= cnt) return;
    const int tid = threadIdx.x;

    if (tid < EBM) {
        int ci = e0 + tid;
        int e = 0, s = 0, r = 0;
        if (ci < cnt) { e = g_active[ci]; s = senders[e]; r = g_crecv[ci]; }
        s_eidx[tid] = e; s_is[tid] = s; s_ir[tid] = r;
    }
    __syncthreads();

    // pre-sum Ps + Pr into s_h + stage edge feats
    for (int idx = tid; idx < EBM * 64; idx += 512) {
        int m = idx >> 6, p = idx & 63;
        const float4 a = *(const float4*)(g_proj + (size_t)s_is[m] * PROJW + p * 4);
        const float4 b = *(const float4*)(g_proj + (size_t)s_ir[m] * PROJW + 256 + p * 4);
        *(float4*)&s_h[m][p * 4] = make_float4(a.x + b.x, a.y + b.y, a.z + b.z, a.w + b.w);
    }
    for (int idx = tid; idx < EBM * 8; idx += 512) {
        int m = idx >> 3, p = idx & 7;
        float4 v = make_float4(0.f, 0.f, 0.f, 0.f);
        if (e0 + m < cnt) v = ((const float4*)(edge_feats + (size_t)s_eidx[m] * ED))[p];
        *(float4*)&s_e[m][p * 4] = v;
    }
    __syncthreads();

    const int tx = tid & 31, ty = tid >> 5;
    const int n0 = tx * 8, m0 = ty * 8;

    // ---- GEMM1 (edge part, K=32) + bias: per-thread 8 rows x 8 cols ----
    u64 acc[8][4];
    {
        const u64* bp = (const u64*)(b1 + n0);
        u64 bv[4] = {bp[0], bp[1], bp[2], bp[3]};
        #pragma unroll
        for (int i = 0; i < 8; i++)
            #pragma unroll
            for (int p = 0; p < 4; p++) acc[i][p] = bv[p];
    }
    const float* W1e = W1 + (size_t)(2 * ND) * HID;
    for (int k = 0; k < ED; k += 4) {
        float av[8][4];
        #pragma unroll
        for (int i = 0; i < 8; i++)
            *(float4*)av[i] = *(const float4*)&s_e[m0 + i][k];
        #pragma unroll
        for (int kk = 0; kk < 4; kk++) {
            const ulonglong2* wp = (const ulonglong2*)(W1e + (k + kk) * HID + n0);
            ulonglong2 w01 = wp[0], w23 = wp[1];
            u64 w[4] = {w01.x, w01.y, w23.x, w23.y};
            #pragma unroll
            for (int i = 0; i < 8; i++) {
                u64 a = pack2(av[i][kk]);
                #pragma unroll
                for (int p = 0; p < 4; p++) acc[i][p] = ffma2(a, w[p], acc[i][p]);
            }
        }
    }

    // h = relu(acc + presummed projections) -> s_h
    #pragma unroll
    for (int i = 0; i < 8; i++) {
        int m = m0 + i;
        #pragma unroll
        for (int g = 0; g < 2; g++) {
            float4 hv = *(float4*)&s_h[m][n0 + g * 4];
            float2 u0 = unpack2(acc[i][2 * g]);
            float2 u1 = unpack2(acc[i][2 * g + 1]);
            float4 r;
            r.x = fmaxf(u0.x + hv.x, 0.f);
            r.y = fmaxf(u0.y + hv.y, 0.f);
            r.z = fmaxf(u1.x + hv.z, 0.f);
            r.w = fmaxf(u1.y + hv.w, 0.f);
            *(float4*)&s_h[m][n0 + g * 4] = r;
        }
    }
    __syncthreads();

    // ---- GEMM2: [128x256] @ [256x128]: per-thread 8 rows x 4 cols ----
    const int c0 = tx * 4;
    u64 acc2[8][2];
    {
        const u64* bp = (const u64*)(b2 + c0);
        u64 b0 = bp[0], b1v = bp[1];
        #pragma unroll
        for (int i = 0; i < 8; i++) { acc2[i][0] = b0; acc2[i][1] = b1v; }
    }
    #pragma unroll 2
    for (int k = 0; k < HID; k += 4) {
        float av[8][4];
        #pragma unroll
        for (int i = 0; i < 8; i++)
            *(float4*)av[i] = *(const float4*)&s_h[m0 + i][k];
        #pragma unroll
        for (int kk = 0; kk < 4; kk++) {
            const ulonglong2* wp = (const ulonglong2*)(W2 + (k + kk) * MSGD + c0);
            ulonglong2 w01 = *wp;
            #pragma unroll
            for (int i = 0; i < 8; i++) {
                u64 a = pack2(av[i][kk]);
                acc2[i][0] = ffma2(a, w01.x, acc2[i][0]);
                acc2[i][1] = ffma2(a, w01.y, acc2[i][1]);
            }
        }
    }

    // relu + gate logits (warp reduce) + direct exp-weighted scatter
    float wg[4];
    *(float4*)wg = *(const float4*)(w_gate + c0);
    const float bg = b_gate[0];

    float v0[8], v1[8], v2[8], v3[8], partial[8];
    #pragma unroll
    for (int i = 0; i < 8; i++) {
        float2 u0 = unpack2(acc2[i][0]);
        float2 u1 = unpack2(acc2[i][1]);
        v0[i] = fmaxf(u0.x, 0.f); v1[i] = fmaxf(u0.y, 0.f);
        v2[i] = fmaxf(u1.x, 0.f); v3[i] = fmaxf(u1.y, 0.f);
        float s = v0[i] * wg[0];
        s = fmaf(v1[i], wg[1], s);
        s = fmaf(v2[i], wg[2], s);
        s = fmaf(v3[i], wg[3], s);
        partial[i] = s;
    }
    #pragma unroll
    for (int o = 16; o >= 1; o >>= 1) {
        #pragma unroll
        for (int i = 0; i < 8; i++)
            partial[i] += __shfl_xor_sync(0xffffffffu, partial[i], o);
    }
    #pragma unroll
    for (int i = 0; i < 8; i++) {
        int ci = e0 + m0 + i;
        if (ci < cnt) {
            float ev = expf(partial[i] + bg);        // max-free softmax weight
            int r = s_ir[m0 + i];
            if (tx == 0) atomicAdd(g_denom + r, ev);
            red_add_v4(g_aggr + (size_t)r * MSGD + c0,
                       make_float4(ev * v0[i], ev * v1[i], ev * v2[i], ev * v3[i]));
        }
    }
}

// ---------------- agent MLP (divides by denom on load) -----------------------
__global__ __launch_bounds__(256, 2) void agent_mlp_kernel(
    const float* __restrict__ W_h1, const float* __restrict__ b_h1,
    const float* __restrict__ W_h2, const float* __restrict__ b_h2,
    const float* __restrict__ W_out, const float* __restrict__ b_out,
    float* __restrict__ out, int n_agents)
{
    extern __shared__ float smem[];
    float (*s_x)[XPAD] = (float (*)[XPAD])smem;
    float (*s_h)[HPAD] = (float (*)[HPAD])(smem + BM * XPAD);

    const int r0 = blockIdx.x * BM;
    const int tid = threadIdx.x;

    for (int idx = tid; idx < BM * 32; idx += 256) {
        int m = idx >> 5, p = idx & 31;
        int r = r0 + m;
        float4 v = make_float4(0.f, 0.f, 0.f, 0.f);
        if (r < n_agents) {
            float inv = __frcp_rn(g_denom[r] + 1e-9f);
            v = *(const float4*)(g_aggr + (size_t)r * MSGD + p * 4);
            v.x *= inv; v.y *= inv; v.z *= inv; v.w *= inv;
        }
        *(float4*)&s_x[m][p * 4] = v;
    }
    __syncthreads();

    const int tx = tid & 31, ty = tid >> 5;
    const int n0 = tx * 8, m0 = ty * 8;

    u64 acc[8][4];
    {
        const u64* bp = (const u64*)(b_h1 + n0);
        u64 bv[4] = {bp[0], bp[1], bp[2], bp[3]};
        #pragma unroll
        for (int i = 0; i < 8; i++)
            #pragma unroll
            for (int p = 0; p < 4; p++) acc[i][p] = bv[p];
    }
    for (int k = 0; k < MSGD; k += 4) {
        float av[8][4];
        #pragma unroll
        for (int i = 0; i < 8; i++)
            *(float4*)av[i] = *(const float4*)&s_x[m0 + i][k];
        #pragma unroll
        for (int kk = 0; kk < 4; kk++) {
            const ulonglong2* wp = (const ulonglong2*)(W_h1 + (k + kk) * HID + n0);
            ulonglong2 w01 = wp[0], w23 = wp[1];
            u64 w[4] = {w01.x, w01.y, w23.x, w23.y};
            #pragma unroll
            for (int i = 0; i < 8; i++) {
                u64 a = pack2(av[i][kk]);
                #pragma unroll
                for (int p = 0; p < 4; p++) acc[i][p] = ffma2(a, w[p], acc[i][p]);
            }
        }
    }
    #pragma unroll
    for (int i = 0; i < 8; i++) {
        #pragma unroll
        for (int g = 0; g < 2; g++) {
            float2 u0 = unpack2(acc[i][2 * g]);
            float2 u1 = unpack2(acc[i][2 * g + 1]);
            float4 r;
            r.x = fmaxf(u0.x, 0.f); r.y = fmaxf(u0.y, 0.f);
            r.z = fmaxf(u1.x, 0.f); r.w = fmaxf(u1.y, 0.f);
            *(float4*)&s_h[m0 + i][n0 + g * 4] = r;
        }
    }
    __syncthreads();

    {
        const u64* bp = (const u64*)(b_h2 + n0);
        u64 bv[4] = {bp[0], bp[1], bp[2], bp[3]};
        #pragma unroll
        for (int i = 0; i < 8; i++)
            #pragma unroll
            for (int p = 0; p < 4; p++) acc[i][p] = bv[p];
    }
    #pragma unroll 2
    for (int k = 0; k < HID; k += 4) {
        float av[8][4];
        #pragma unroll
        for (int i = 0; i < 8; i++)
            *(float4*)av[i] = *(const float4*)&s_h[m0 + i][k];
        #pragma unroll
        for (int kk = 0; kk < 4; kk++) {
            const ulonglong2* wp = (const ulonglong2*)(W_h2 + (k + kk) * HID + n0);
            ulonglong2 w01 = wp[0], w23 = wp[1];
            u64 w[4] = {w01.x, w01.y, w23.x, w23.y};
            #pragma unroll
            for (int i = 0; i < 8; i++) {
                u64 a = pack2(av[i][kk]);
                #pragma unroll
                for (int p = 0; p < 4; p++) acc[i][p] = ffma2(a, w[p], acc[i][p]);
            }
        }
    }

    float wo[8];
    *(float4*)&wo[0] = *(const float4*)(W_out + n0);
    *(float4*)&wo[4] = *(const float4*)(W_out + n0 + 4);
    float partial[8];
    #pragma unroll
    for (int i = 0; i < 8; i++) {
        float s = 0.f;
        #pragma unroll
        for (int p = 0; p < 4; p++) {
            float2 u = unpack2(acc[i][p]);
            s = fmaf(fmaxf(u.x, 0.f), wo[2 * p], s);
            s = fmaf(fmaxf(u.y, 0.f), wo[2 * p + 1], s);
        }
        partial[i] = s;
    }
    #pragma unroll
    for (int o = 16; o >= 1; o >>= 1) {
        #pragma unroll
        for (int i = 0; i < 8; i++)
            partial[i] += __shfl_xor_sync(0xffffffffu, partial[i], o);
    }
    if (tx == 0) {
        float bo = b_out[0];
        #pragma unroll
        for (int i = 0; i < 8; i++) {
            int r = r0 + m0 + i;
            if (r < n_agents) out[r] = tanhf(partial[i] + bo);
        }
    }
}

// ---------------------------------------------------------------------------
extern "C" void kernel_launch(void* const* d_in, const int* in_sizes, int n_in,
                              void* d_out, int out_size) {
    const float* node_feats = (const float*)d_in[0];
    const float* edge_feats = (const float*)d_in[1];
    const float* W_msg1 = (const float*)d_in[2];
    const float* b_msg1 = (const float*)d_in[3];
    const float* W_msg2 = (const float*)d_in[4];
    const float* b_msg2 = (const float*)d_in[5];
    const float* w_gate = (const float*)d_in[6];
    const float* b_gate = (const float*)d_in[7];
    const float* W_h1   = (const float*)d_in[8];
    const float* b_h1   = (const float*)d_in[9];
    const float* W_h2   = (const float*)d_in[10];
    const float* b_h2   = (const float*)d_in[11];
    const float* W_out  = (const float*)d_in[12];
    const float* b_out  = (const float*)d_in[13];
    const int* senders   = (const int*)d_in[14];
    const int* receivers = (const int*)d_in[15];
    float* out = (float*)d_out;

    const int n_edges  = in_sizes[14];
    const int n_nodes  = in_sizes[0] / ND;
    const int n_agents = out_size;

    const int SMEM_EDGE  = (EBM * EPAD + EBM * HPAD) * (int)sizeof(float) + 3 * EBM * (int)sizeof(int);
    const int SMEM_AGENT = (BM * XPAD + BM * HPAD) * (int)sizeof(float);
    cudaFuncSetAttribute(edge_mlp_kernel, cudaFuncAttributeMaxDynamicSharedMemorySize, SMEM_EDGE);
    cudaFuncSetAttribute(agent_mlp_kernel, cudaFuncAttributeMaxDynamicSharedMemorySize, SMEM_AGENT);

    {
        int total = n_agents * MSGD;
        init_kernel<<<(total + 255) / 256, 256>>>(n_agents);
    }
    compact_kernel<<<(n_edges + 255) / 256, 256>>>(receivers, n_edges, n_agents);
    {
        dim3 grid((n_nodes + BM - 1) / BM, 2);
        node_proj_kernel<<<grid, 256>>>(node_feats, W_msg1, n_nodes, n_agents);
    }
    {
        int grid = (n_edges + EBM - 1) / EBM;
        edge_mlp_kernel<<<grid, 512, SMEM_EDGE>>>(
            edge_feats, W_msg1, b_msg1, W_msg2, b_msg2, w_gate, b_gate, senders);
    }
    agent_mlp_kernel<<<(n_agents + BM - 1) / BM, 256, SMEM_AGENT>>>(
        W_h1, b_h1, W_h2, b_h2, W_out, b_out, out, n_agents);
}